// round 7
// baseline (speedup 1.0000x reference)
#include <cuda_runtime.h>
#include <cuda_bf16.h>
#include <cstdint>

#define MROWS   65536
#define DFEAT   512
#define NEDGES  65536
#define NGRAPH  16
#define GSHIFT  12          // rows per graph = 4096

// ---------------------------------------------------------------------------
// Scratch (__device__ globals; allocation-free)
// ---------------------------------------------------------------------------
__device__ float g_support[(size_t)MROWS * DFEAT];
__device__ float g_S[MROWS];
__device__ float g_rt[NGRAPH * DFEAT];
__device__ float g_rt2[NGRAPH * DFEAT];
__device__ float g_h1root[NGRAPH * DFEAT];
__device__ __nv_bfloat16 g_ah[(size_t)MROWS * DFEAT], g_al[(size_t)MROWS * DFEAT];
__device__ __nv_bfloat16 g_bh[(size_t)MROWS * DFEAT], g_bl[(size_t)MROWS * DFEAT];
__device__ __nv_bfloat16 g_w1h[512 * 512], g_w1l[512 * 512];
__device__ __nv_bfloat16 g_w2h[512 * 512], g_w2l[512 * 512];
__device__ __nv_bfloat16 g_wlh[512 * 512], g_wll[512 * 512];
// CSR
__device__ int   g_cnt[MROWS];
__device__ int   g_offs[MROWS + 1];
__device__ int   g_cursor[MROWS];
__device__ int   g_ecol[NEDGES];
__device__ float g_ew[NEDGES];

// ---------------------------------------------------------------------------
// PTX helpers
// ---------------------------------------------------------------------------
__device__ __forceinline__ uint32_t smem_u32(const void* p) {
    return (uint32_t)__cvta_generic_to_shared(p);
}
__device__ __forceinline__ void cp_async16(uint32_t dst, const void* src) {
    asm volatile("cp.async.cg.shared.global [%0], [%1], 16;" :: "r"(dst), "l"(src));
}
__device__ __forceinline__ void cp_commit() {
    asm volatile("cp.async.commit_group;");
}
template<int N>
__device__ __forceinline__ void cp_wait() {
    asm volatile("cp.async.wait_group %0;" :: "n"(N));
}
__device__ __forceinline__ void ldsm_x4(uint32_t& r0, uint32_t& r1,
                                        uint32_t& r2, uint32_t& r3, uint32_t a) {
    asm volatile("ldmatrix.sync.aligned.m8n8.x4.shared.b16 {%0,%1,%2,%3}, [%4];"
                 : "=r"(r0), "=r"(r1), "=r"(r2), "=r"(r3) : "r"(a));
}
__device__ __forceinline__ void mma16816(float* c, const uint32_t* a, const uint32_t* b) {
    asm volatile(
        "mma.sync.aligned.m16n8k16.row.col.f32.bf16.bf16.f32 "
        "{%0,%1,%2,%3}, {%4,%5,%6,%7}, {%8,%9}, {%0,%1,%2,%3};"
        : "+f"(c[0]), "+f"(c[1]), "+f"(c[2]), "+f"(c[3])
        : "r"(a[0]), "r"(a[1]), "r"(a[2]), "r"(a[3]), "r"(b[0]), "r"(b[1]));
}

// ---------------------------------------------------------------------------
// split helpers
// ---------------------------------------------------------------------------
__device__ __forceinline__ void split1(float x, __nv_bfloat16& h, __nv_bfloat16& l) {
    h = __float2bfloat16_rn(x);
    l = __float2bfloat16_rn(x - __bfloat162float(h));
}
__device__ __forceinline__ void split_store2(__nv_bfloat16* ph, __nv_bfloat16* pl, float2 v) {
    __nv_bfloat16 h0, l0, h1, l1;
    split1(v.x, h0, l0); split1(v.y, h1, l1);
    __nv_bfloat162 hh, ll;
    hh.x = h0; hh.y = h1; ll.x = l0; ll.y = l1;
    *(__nv_bfloat162*)ph = hh; *(__nv_bfloat162*)pl = ll;
}
__device__ __forceinline__ void split_store4(__nv_bfloat16* ph, __nv_bfloat16* pl, float4 v) {
    split_store2(ph,     pl,     make_float2(v.x, v.y));
    split_store2(ph + 2, pl + 2, make_float2(v.z, v.w));
}

// ---------------------------------------------------------------------------
// bf16x3 split GEMM: C = (Ah+Al)[M,512] @ (Bh+Bl)[512,512]^T
// CTA 128x256, 256 threads, 8 warps of 64x64, BK=64, 4-stage cp.async.
// EPI=0: plain fp32 store -> C
// EPI=4: +bias(col)+S[row]*rt[g,col]; relu; split->Oh/Ol
// EPI=2: +rt2[g,col]; leaky_relu; fp32 store -> C
// ---------------------------------------------------------------------------
#define BM2 128
#define BN2 256
#define NSTAGE 4
#define SMA (BM2 * 128)
#define SMB (BN2 * 128)
#define SMSTAGE (SMA + SMB)
#define SMTOTAL (NSTAGE * SMSTAGE + 1024)

template<int EPI>
__global__ void __launch_bounds__(256, 1)
gemm_bf16x3(const __nv_bfloat16* __restrict__ Ah, const __nv_bfloat16* __restrict__ Al,
            const __nv_bfloat16* __restrict__ Bh, const __nv_bfloat16* __restrict__ Bl,
            float* __restrict__ C,
            __nv_bfloat16* __restrict__ Oh, __nv_bfloat16* __restrict__ Ol,
            const float* __restrict__ bias, const float* __restrict__ rt,
            const float* __restrict__ S)
{
    constexpr int K = 512;
    extern __shared__ char dsm[];
    uint32_t sb = (smem_u32(dsm) + 1023) & ~1023u;

    const int tid  = threadIdx.x;
    const int lane = tid & 31;
    const int wid  = tid >> 5;
    const int wm   = wid & 1;          // 2 warps along M (64 rows each)
    const int wn   = wid >> 1;         // 4 warps along N (64 cols each)
    const long bm  = (long)blockIdx.y * BM2;
    const long bn  = (long)blockIdx.x * BN2;

    const __nv_bfloat16* Aseg[3] = {Ah, Ah, Al};
    const __nv_bfloat16* Bseg[3] = {Bh, Bl, Bh};
    const int cps = K >> 6;            // 8
    const int nch = 3 * cps;           // 24

    float c[4][8][4];
#pragma unroll
    for (int i = 0; i < 4; i++)
#pragma unroll
        for (int j = 0; j < 8; j++)
#pragma unroll
            for (int q = 0; q < 4; q++) c[i][j][q] = 0.0f;

    const int amat  = lane >> 3;
    const int arow0 = wm * 64 + (amat & 1) * 8 + (lane & 7);
    const int ahalf = amat >> 1;
    const int bg    = lane >> 3;
    const int bhalf = bg & 1;
    const int bn0   = wn * 64 + ((bg >> 1) << 3) + (lane & 7);

    auto loads = [&](int ch, int s) {
        int seg = (ch >= 2 * cps) ? 2 : ((ch >= cps) ? 1 : 0);
        int kk  = (ch - seg * cps) << 6;
        const __nv_bfloat16* Ab = Aseg[seg] + bm * K + kk;
        const __nv_bfloat16* Bb = Bseg[seg] + bn * K + kk;
        uint32_t As = sb + s * SMSTAGE;
        uint32_t Bs = As + SMA;
#pragma unroll
        for (int i = 0; i < 4; i++) {              // A: 128 rows x 8 16B-chunks
            int lin = tid * 4 + i;
            int r = lin >> 3, cc = lin & 7;
            cp_async16(As + r * 128 + ((cc ^ (r & 7)) << 4), Ab + (long)r * K + cc * 8);
        }
#pragma unroll
        for (int i = 0; i < 8; i++) {              // B: 256 rows x 8 16B-chunks
            int lin = tid * 8 + i;
            int r = lin >> 3, cc = lin & 7;
            cp_async16(Bs + r * 128 + ((cc ^ (r & 7)) << 4), Bb + (long)r * K + cc * 8);
        }
    };

    loads(0, 0); cp_commit();
    loads(1, 1); cp_commit();
    loads(2, 2); cp_commit();

    for (int k = 0; k < nch; k++) {
        cp_wait<2>();
        __syncthreads();
        if (k + 3 < nch) loads(k + 3, (k + 3) & (NSTAGE - 1));
        cp_commit();

        uint32_t As = sb + (k & (NSTAGE - 1)) * SMSTAGE;
        uint32_t Bs = As + SMA;
#pragma unroll
        for (int t = 0; t < 4; t++) {
            uint32_t a[4][4];
#pragma unroll
            for (int mi = 0; mi < 4; mi++) {
                int row = arow0 + mi * 16;
                uint32_t addr = As + row * 128 + ((((2 * t) + ahalf) ^ (row & 7)) << 4);
                ldsm_x4(a[mi][0], a[mi][1], a[mi][2], a[mi][3], addr);
            }
            uint32_t b[8][2];
#pragma unroll
            for (int j = 0; j < 4; j++) {
                int n = bn0 + j * 16;
                uint32_t addr = Bs + n * 128 + ((((2 * t) + bhalf) ^ (n & 7)) << 4);
                ldsm_x4(b[2 * j][0], b[2 * j][1], b[2 * j + 1][0], b[2 * j + 1][1], addr);
            }
#pragma unroll
            for (int mi = 0; mi < 4; mi++)
#pragma unroll
                for (int nj = 0; nj < 8; nj++)
                    mma16816(c[mi][nj], a[mi], b[nj]);
        }
    }

#pragma unroll
    for (int mi = 0; mi < 4; mi++) {
        long row = bm + wm * 64 + mi * 16 + (lane >> 2);
        int g = (int)(row >> GSHIFT);
#pragma unroll
        for (int nj = 0; nj < 8; nj++) {
            int col = (int)bn + wn * 64 + nj * 8 + 2 * (lane & 3);
            float2 v0 = {c[mi][nj][0], c[mi][nj][1]};   // row
            float2 v1 = {c[mi][nj][2], c[mi][nj][3]};   // row + 8

            if (EPI == 0) {
                *(float2*)(C + row * 512 + col)       = v0;
                *(float2*)(C + (row + 8) * 512 + col) = v1;
            } else if (EPI == 4) {
                float s0 = S[row], s1 = S[row + 8];
                float r0 = rt[g * 512 + col], r1 = rt[g * 512 + col + 1];
                float b0 = bias[col], b1v = bias[col + 1];
                v0.x += b0 + s0 * r0; v0.y += b1v + s0 * r1;
                v1.x += b0 + s1 * r0; v1.y += b1v + s1 * r1;
                v0.x = fmaxf(v0.x, 0.f); v0.y = fmaxf(v0.y, 0.f);
                v1.x = fmaxf(v1.x, 0.f); v1.y = fmaxf(v1.y, 0.f);
                split_store2(Oh + row * 512 + col,       Ol + row * 512 + col,       v0);
                split_store2(Oh + (row + 8) * 512 + col, Ol + (row + 8) * 512 + col, v1);
            } else {  // EPI == 2
                float b0 = rt[g * 512 + col], b1v = rt[g * 512 + col + 1];
                v0.x += b0; v0.y += b1v; v1.x += b0; v1.y += b1v;
                v0.x = (v0.x >= 0.f) ? v0.x : 0.01f * v0.x;
                v0.y = (v0.y >= 0.f) ? v0.y : 0.01f * v0.y;
                v1.x = (v1.x >= 0.f) ? v1.x : 0.01f * v1.x;
                v1.y = (v1.y >= 0.f) ? v1.y : 0.01f * v1.y;
                *(float2*)(C + row * 512 + col)       = v0;
                *(float2*)(C + (row + 8) * 512 + col) = v1;
            }
        }
    }
}

// ---------------------------------------------------------------------------
// prep: split W1/W2a/Wla (transposed) + split X + zero CSR histogram
// ---------------------------------------------------------------------------
__global__ void prep_kernel(const float* __restrict__ feat,
                            const float* __restrict__ W1,
                            const float* __restrict__ W2,
                            const float* __restrict__ Wl,
                            __nv_bfloat16* __restrict__ ah, __nv_bfloat16* __restrict__ al,
                            __nv_bfloat16* __restrict__ w1h, __nv_bfloat16* __restrict__ w1l,
                            __nv_bfloat16* __restrict__ w2h, __nv_bfloat16* __restrict__ w2l,
                            __nv_bfloat16* __restrict__ wlh, __nv_bfloat16* __restrict__ wll,
                            int* __restrict__ cnt)
{
    long idx = (long)blockIdx.x * blockDim.x + threadIdx.x;
    if (idx < MROWS) cnt[idx] = 0;
    if (idx < 3 * 512 * 512) {
        int which = (int)(idx >> 18);
        int loc   = (int)(idx & 0x3FFFF);
        int n = loc >> 9;
        int k = loc & 511;
        const float* W = (which == 0) ? W1 : (which == 1) ? W2 : Wl;
        __nv_bfloat16* wh = (which == 0) ? w1h : (which == 1) ? w2h : wlh;
        __nv_bfloat16* wl = (which == 0) ? w1l : (which == 1) ? w2l : wll;
        float x = __ldg(&W[(long)k * 512 + n]);
        __nv_bfloat16 h, l;
        split1(x, h, l);
        wh[loc] = h; wl[loc] = l;
    }
    if (idx < (long)MROWS * 128) {
        float4 v = ((const float4*)feat)[idx];
        split_store4(ah + idx * 4, al + idx * 4, v);
    }
}

// ---------------------------------------------------------------------------
// CSR build
// ---------------------------------------------------------------------------
__global__ void hist_kernel(const int* __restrict__ rows, int* __restrict__ cnt, int nE)
{
    int e = blockIdx.x * blockDim.x + threadIdx.x;
    if (e < nE) atomicAdd(&cnt[rows[e]], 1);
}
__global__ void __launch_bounds__(1024, 1)
scan_kernel(const int* __restrict__ cnt, int* __restrict__ offs, int* __restrict__ cursor)
{
    __shared__ int ts[1024];
    const int tid = threadIdx.x;
    const int base = tid * 64;
    int local = 0;
#pragma unroll 8
    for (int i = 0; i < 64; i++) local += cnt[base + i];
    int x = local;
    ts[tid] = x; __syncthreads();
    for (int s = 1; s < 1024; s <<= 1) {
        int v = (tid >= s) ? ts[tid - s] : 0;
        __syncthreads();
        x += v; ts[tid] = x; __syncthreads();
    }
    int run = x - local;
    for (int i = 0; i < 64; i++) {
        int cc = cnt[base + i];
        offs[base + i] = run;
        cursor[base + i] = run;
        run += cc;
    }
    if (tid == 1023) offs[MROWS] = run;
}
__global__ void fill_csr_kernel(const int* __restrict__ rows, const int* __restrict__ cols,
                                const float* __restrict__ vals, int* __restrict__ cursor,
                                int* __restrict__ ecol, float* __restrict__ ew, int nE)
{
    int e = blockIdx.x * blockDim.x + threadIdx.x;
    if (e >= nE) return;
    int p = atomicAdd(&cursor[rows[e]], 1);
    ecol[p] = cols[e];
    ew[p]   = vals[e];
}

// ---------------------------------------------------------------------------
// fused gather for layer 1: h1[r] = b1 + sum_e w_e * support[col_e]
// also: S[r], h1root (pre-relu at root rows), relu+split -> oh/ol
// ---------------------------------------------------------------------------
__global__ void __launch_bounds__(128)
gather_h1_kernel(const float* __restrict__ support, const int* __restrict__ offs,
                 const int* __restrict__ ecol, const float* __restrict__ ew,
                 const float* __restrict__ b1, const int* __restrict__ root_idx,
                 __nv_bfloat16* __restrict__ oh, __nv_bfloat16* __restrict__ ol,
                 float* __restrict__ h1root, float* __restrict__ S)
{
    const int r = blockIdx.x;
    const int tid = threadIdx.x;
    const int beg = __ldg(&offs[r]), end = __ldg(&offs[r + 1]);
    float4 acc = make_float4(0.f, 0.f, 0.f, 0.f);
    float s = 0.f;
    int i = beg;
    for (; i + 4 <= end; i += 4) {
        int c0 = __ldg(&ecol[i]),   c1 = __ldg(&ecol[i+1]);
        int c2 = __ldg(&ecol[i+2]), c3 = __ldg(&ecol[i+3]);
        float w0 = __ldg(&ew[i]),   w1 = __ldg(&ew[i+1]);
        float w2 = __ldg(&ew[i+2]), w3 = __ldg(&ew[i+3]);
        float4 v0 = __ldg((const float4*)(support + (long)c0 * 512) + tid);
        float4 v1 = __ldg((const float4*)(support + (long)c1 * 512) + tid);
        float4 v2 = __ldg((const float4*)(support + (long)c2 * 512) + tid);
        float4 v3 = __ldg((const float4*)(support + (long)c3 * 512) + tid);
        acc.x += w0*v0.x + w1*v1.x + w2*v2.x + w3*v3.x;
        acc.y += w0*v0.y + w1*v1.y + w2*v2.y + w3*v3.y;
        acc.z += w0*v0.z + w1*v1.z + w2*v2.z + w3*v3.z;
        acc.w += w0*v0.w + w1*v1.w + w2*v2.w + w3*v3.w;
        s += w0 + w1 + w2 + w3;
    }
    for (; i < end; i++) {
        int cc = __ldg(&ecol[i]);
        float w = __ldg(&ew[i]);
        float4 v = __ldg((const float4*)(support + (long)cc * 512) + tid);
        acc.x += w * v.x; acc.y += w * v.y; acc.z += w * v.z; acc.w += w * v.w;
        s += w;
    }
    float4 bb = __ldg((const float4*)b1 + tid);
    acc.x += bb.x; acc.y += bb.y; acc.z += bb.z; acc.w += bb.w;
    if (tid == 0) S[r] = s;
    int g = r >> GSHIFT;
    if (__ldg(&root_idx[g]) == r)
        ((float4*)(h1root + g * 512))[tid] = acc;     // pre-relu
    acc.x = fmaxf(acc.x, 0.f); acc.y = fmaxf(acc.y, 0.f);
    acc.z = fmaxf(acc.z, 0.f); acc.w = fmaxf(acc.w, 0.f);
    split_store4(oh + (long)r * 512 + tid * 4, ol + (long)r * 512 + tid * 4, acc);
}

// ---------------------------------------------------------------------------
// gather for layer 2 (bf16 split input -> bf16 split output)
// ---------------------------------------------------------------------------
__device__ __forceinline__ float4 ld_bf16pair(const __nv_bfloat16* sh,
                                              const __nv_bfloat16* sl,
                                              long row, int tid)
{
    const __nv_bfloat162* ph = (const __nv_bfloat162*)(sh + row * 512) + tid * 2;
    const __nv_bfloat162* pl = (const __nv_bfloat162*)(sl + row * 512) + tid * 2;
    __nv_bfloat162 h0 = __ldg(ph), h1 = __ldg(ph + 1);
    __nv_bfloat162 l0 = __ldg(pl), l1 = __ldg(pl + 1);
    float4 v;
    v.x = __bfloat162float(h0.x) + __bfloat162float(l0.x);
    v.y = __bfloat162float(h0.y) + __bfloat162float(l0.y);
    v.z = __bfloat162float(h1.x) + __bfloat162float(l1.x);
    v.w = __bfloat162float(h1.y) + __bfloat162float(l1.y);
    return v;
}

__global__ void __launch_bounds__(128)
gather_bf16_kernel(const __nv_bfloat16* __restrict__ sh, const __nv_bfloat16* __restrict__ sl,
                   const int* __restrict__ offs, const int* __restrict__ ecol,
                   const float* __restrict__ ew,
                   __nv_bfloat16* __restrict__ oh, __nv_bfloat16* __restrict__ ol)
{
    const int r = blockIdx.x;
    const int tid = threadIdx.x;
    const int beg = __ldg(&offs[r]), end = __ldg(&offs[r + 1]);
    float4 acc = make_float4(0.f, 0.f, 0.f, 0.f);
    int i = beg;
    for (; i + 4 <= end; i += 4) {
        int c0 = __ldg(&ecol[i]),   c1 = __ldg(&ecol[i+1]);
        int c2 = __ldg(&ecol[i+2]), c3 = __ldg(&ecol[i+3]);
        float w0 = __ldg(&ew[i]),   w1 = __ldg(&ew[i+1]);
        float w2 = __ldg(&ew[i+2]), w3 = __ldg(&ew[i+3]);
        float4 v0 = ld_bf16pair(sh, sl, c0, tid);
        float4 v1 = ld_bf16pair(sh, sl, c1, tid);
        float4 v2 = ld_bf16pair(sh, sl, c2, tid);
        float4 v3 = ld_bf16pair(sh, sl, c3, tid);
        acc.x += w0*v0.x + w1*v1.x + w2*v2.x + w3*v3.x;
        acc.y += w0*v0.y + w1*v1.y + w2*v2.y + w3*v3.y;
        acc.z += w0*v0.z + w1*v1.z + w2*v2.z + w3*v3.z;
        acc.w += w0*v0.w + w1*v1.w + w2*v2.w + w3*v3.w;
    }
    for (; i < end; i++) {
        int cc = __ldg(&ecol[i]);
        float w = __ldg(&ew[i]);
        float4 v = ld_bf16pair(sh, sl, cc, tid);
        acc.x += w * v.x; acc.y += w * v.y; acc.z += w * v.z; acc.w += w * v.w;
    }
    split_store4(oh + (long)r * 512 + tid * 4, ol + (long)r * 512 + tid * 4, acc);
}

// ---------------------------------------------------------------------------
// root terms
// ---------------------------------------------------------------------------
__global__ void init_rt_kernel(float* __restrict__ rt, float* __restrict__ rt2,
                               const float* __restrict__ bl)
{
    int idx = blockIdx.x * blockDim.x + threadIdx.x;
    if (idx >= NGRAPH * DFEAT) return;
    rt[idx] = 0.f;
    rt2[idx] = bl[idx & 511];
}
__global__ void __launch_bounds__(512)
root_term_kernel(const float* __restrict__ feat, const int* __restrict__ root_idx,
                 const float* __restrict__ W2, float* __restrict__ rt)
{
    int g  = blockIdx.x;
    int kc = blockIdx.y << 6;
    int n  = threadIdx.x;
    const float* v  = feat + (long)root_idx[g] * DFEAT + kc;
    const float* Wb = W2 + (long)(512 + kc) * 512 + n;
    float acc = 0.f;
#pragma unroll 8
    for (int k = 0; k < 64; k++)
        acc += fmaxf(__ldg(v + k), 0.f) * __ldg(Wb + (long)k * 512);
    atomicAdd(&rt[g * DFEAT + n], acc);
}
__global__ void __launch_bounds__(512)
root_term2_kernel(const float* __restrict__ h1root, const float* __restrict__ Wl,
                  float* __restrict__ rt2)
{
    int g  = blockIdx.x;
    int kc = blockIdx.y << 6;
    int n  = threadIdx.x;
    const float* v  = h1root + g * DFEAT + kc;
    const float* Wb = Wl + (long)(512 + kc) * 512 + n;
    float acc = 0.f;
#pragma unroll 8
    for (int k = 0; k < 64; k++)
        acc += __ldg(v + k) * __ldg(Wb + (long)k * 512);
    atomicAdd(&rt2[g * DFEAT + n], acc);
}

// ---------------------------------------------------------------------------
// launch  (gemm1 at my index 3 -> ncu -s 5 lands on it)
// ---------------------------------------------------------------------------
extern "C" void kernel_launch(void* const* d_in, const int* in_sizes, int n_in,
                              void* d_out, int out_size)
{
    const float* features = (const float*)d_in[0];
    const int*   adjs     = (const int*)  d_in[1];
    const float* values   = (const float*)d_in[2];
    const int*   root_idx = (const int*)  d_in[3];
    const float* W1 = (const float*)d_in[6];
    const float* b1 = (const float*)d_in[7];
    const float* W2 = (const float*)d_in[8];
    const float* b2 = (const float*)d_in[9];
    const float* Wl = (const float*)d_in[10];
    const float* bl = (const float*)d_in[11];
    float* out = (float*)d_out;

    const int nE = in_sizes[2];

    float *support, *S, *rt, *rt2, *h1root, *ew;
    int *cnt, *offs, *cursor, *ecol;
    __nv_bfloat16 *ah, *al, *bh, *blo, *w1h, *w1l, *w2h, *w2l, *wlh, *wll;
    cudaGetSymbolAddress((void**)&support, g_support);
    cudaGetSymbolAddress((void**)&S,      g_S);
    cudaGetSymbolAddress((void**)&rt,     g_rt);
    cudaGetSymbolAddress((void**)&rt2,    g_rt2);
    cudaGetSymbolAddress((void**)&h1root, g_h1root);
    cudaGetSymbolAddress((void**)&cnt,    g_cnt);
    cudaGetSymbolAddress((void**)&offs,   g_offs);
    cudaGetSymbolAddress((void**)&cursor, g_cursor);
    cudaGetSymbolAddress((void**)&ecol,   g_ecol);
    cudaGetSymbolAddress((void**)&ew,     g_ew);
    cudaGetSymbolAddress((void**)&ah,  g_ah);
    cudaGetSymbolAddress((void**)&al,  g_al);
    cudaGetSymbolAddress((void**)&bh,  g_bh);
    cudaGetSymbolAddress((void**)&blo, g_bl);
    cudaGetSymbolAddress((void**)&w1h, g_w1h);
    cudaGetSymbolAddress((void**)&w1l, g_w1l);
    cudaGetSymbolAddress((void**)&w2h, g_w2h);
    cudaGetSymbolAddress((void**)&w2l, g_w2l);
    cudaGetSymbolAddress((void**)&wlh, g_wlh);
    cudaGetSymbolAddress((void**)&wll, g_wll);

    const int* rows = adjs;
    const int* cols = adjs + nE;

    cudaFuncSetAttribute(gemm_bf16x3<0>, cudaFuncAttributeMaxDynamicSharedMemorySize, SMTOTAL);
    cudaFuncSetAttribute(gemm_bf16x3<4>, cudaFuncAttributeMaxDynamicSharedMemorySize, SMTOTAL);
    cudaFuncSetAttribute(gemm_bf16x3<2>, cudaFuncAttributeMaxDynamicSharedMemorySize, SMTOTAL);

    dim3 ggrid(DFEAT / BN2, MROWS / BM2);             // (2, 512)
    dim3 rtg(NGRAPH, 8);

    // #0: prep (W splits, X split, cnt zero)
    prep_kernel<<<(int)(((long)MROWS * 128 + 255) / 256), 256>>>(
        features, W1, W2, Wl, ah, al, w1h, w1l, w2h, w2l, wlh, wll, cnt);
    // #1-2: CSR hist + scan
    hist_kernel<<<(nE + 255) / 256, 256>>>(rows, cnt, nE);
    scan_kernel<<<1, 1024>>>(cnt, offs, cursor);
    // #3: GEMM1: support = X @ W1  (fp32 out)           <-- ncu -s 5 target
    gemm_bf16x3<0><<<ggrid, 256, SMTOTAL>>>(ah, al, w1h, w1l, support,
                                            nullptr, nullptr, nullptr, nullptr, nullptr);
    // #4: CSR fill
    fill_csr_kernel<<<(nE + 255) / 256, 256>>>(rows, cols, values, cursor, ecol, ew, nE);
    // #5: h1 = b1 + P@support; S; h1root; relu-split -> bh/blo
    gather_h1_kernel<<<MROWS, 128>>>(support, offs, ecol, ew, b1, root_idx,
                                     bh, blo, h1root, S);
    // #6-8: root terms
    init_rt_kernel<<<(NGRAPH * DFEAT + 255) / 256, 256>>>(rt, rt2, bl);
    root_term_kernel<<<rtg, 512>>>(features, root_idx, W2, rt);
    root_term2_kernel<<<rtg, 512>>>(h1root, Wl, rt2);
    // #9: Y = P @ relu(h1)  (split bf16) -> ah/al
    gather_bf16_kernel<<<MROWS, 128>>>(bh, blo, offs, ecol, ew, ah, al);
    // #10: h2 = Y @ W2a + b2 + S*rt[g]; relu; split -> bh/blo
    gemm_bf16x3<4><<<ggrid, 256, SMTOTAL>>>(ah, al, w2h, w2l, nullptr,
                                            bh, blo, b2, rt, S);
    // #11: out = leaky_relu(relu(h2) @ Wla + rt2[g])
    gemm_bf16x3<2><<<ggrid, 256, SMTOTAL>>>(bh, blo, wlh, wll, out,
                                            nullptr, nullptr, nullptr, rt2, nullptr);
}

// round 8
// speedup vs baseline: 1.2284x; 1.2284x over previous
#include <cuda_runtime.h>
#include <cuda_bf16.h>
#include <cstdint>

#define MROWS   65536
#define DFEAT   512
#define NEDGES  65536
#define NGRAPH  16
#define GSHIFT  12          // rows per graph = 4096

// ---------------------------------------------------------------------------
// Scratch (__device__ globals; allocation-free)
// ---------------------------------------------------------------------------
__device__ float g_S[MROWS];
__device__ float g_rt[NGRAPH * DFEAT];
__device__ float g_rt2[NGRAPH * DFEAT];
__device__ float g_h1root[NGRAPH * DFEAT];
__device__ __nv_bfloat16 g_ah[(size_t)MROWS * DFEAT], g_al[(size_t)MROWS * DFEAT];
__device__ __nv_bfloat16 g_bh[(size_t)MROWS * DFEAT], g_bl[(size_t)MROWS * DFEAT];
__device__ __nv_bfloat16 g_w1h[512 * 512], g_w1l[512 * 512];
__device__ __nv_bfloat16 g_w2h[512 * 512], g_w2l[512 * 512];
__device__ __nv_bfloat16 g_wlh[512 * 512], g_wll[512 * 512];
// CSR
__device__ int   g_cnt[MROWS];
__device__ int   g_offs[MROWS + 1];
__device__ int   g_cursor[MROWS];
__device__ int   g_ecol[NEDGES];
__device__ float g_ew[NEDGES];

// ---------------------------------------------------------------------------
// PTX helpers
// ---------------------------------------------------------------------------
__device__ __forceinline__ uint32_t smem_u32(const void* p) {
    return (uint32_t)__cvta_generic_to_shared(p);
}
__device__ __forceinline__ void cp_async16(uint32_t dst, const void* src) {
    asm volatile("cp.async.cg.shared.global [%0], [%1], 16;" :: "r"(dst), "l"(src));
}
__device__ __forceinline__ void cp_commit() {
    asm volatile("cp.async.commit_group;");
}
template<int N>
__device__ __forceinline__ void cp_wait() {
    asm volatile("cp.async.wait_group %0;" :: "n"(N));
}
__device__ __forceinline__ void ldsm_x4(uint32_t& r0, uint32_t& r1,
                                        uint32_t& r2, uint32_t& r3, uint32_t a) {
    asm volatile("ldmatrix.sync.aligned.m8n8.x4.shared.b16 {%0,%1,%2,%3}, [%4];"
                 : "=r"(r0), "=r"(r1), "=r"(r2), "=r"(r3) : "r"(a));
}
__device__ __forceinline__ void mma16816(float* c, const uint32_t* a, const uint32_t* b) {
    asm volatile(
        "mma.sync.aligned.m16n8k16.row.col.f32.bf16.bf16.f32 "
        "{%0,%1,%2,%3}, {%4,%5,%6,%7}, {%8,%9}, {%0,%1,%2,%3};"
        : "+f"(c[0]), "+f"(c[1]), "+f"(c[2]), "+f"(c[3])
        : "r"(a[0]), "r"(a[1]), "r"(a[2]), "r"(a[3]), "r"(b[0]), "r"(b[1]));
}

// ---------------------------------------------------------------------------
// split helpers
// ---------------------------------------------------------------------------
__device__ __forceinline__ void split1(float x, __nv_bfloat16& h, __nv_bfloat16& l) {
    h = __float2bfloat16_rn(x);
    l = __float2bfloat16_rn(x - __bfloat162float(h));
}
__device__ __forceinline__ void split_store2(__nv_bfloat16* ph, __nv_bfloat16* pl, float2 v) {
    __nv_bfloat16 h0, l0, h1, l1;
    split1(v.x, h0, l0); split1(v.y, h1, l1);
    __nv_bfloat162 hh, ll;
    hh.x = h0; hh.y = h1; ll.x = l0; ll.y = l1;
    *(__nv_bfloat162*)ph = hh; *(__nv_bfloat162*)pl = ll;
}
__device__ __forceinline__ void split_store4(__nv_bfloat16* ph, __nv_bfloat16* pl, float4 v) {
    split_store2(ph,     pl,     make_float2(v.x, v.y));
    split_store2(ph + 2, pl + 2, make_float2(v.z, v.w));
}

// ---------------------------------------------------------------------------
// bf16x3 split GEMM: C = (Ah+Al)[M,512] @ (Bh+Bl)[512,512]^T
// CTA 128x128, 256 threads (8 warps of 32x64), BK=64, 3-stage cp.async,
// 2 CTAs per SM (16 warps/SM).
// EPI=3: +bias(col); fp32 root-row store; relu; split->Oh/Ol
// EPI=4: +bias(col)+S[row]*rt[g,col]; relu; split->Oh/Ol
// EPI=2: +rt2[g,col]; leaky_relu; fp32 store -> C
// ---------------------------------------------------------------------------
#define BM2 128
#define BN2 128
#define NSTAGE 3
#define SMA (BM2 * 128)            // 16 KB
#define SMB (BN2 * 128)            // 16 KB
#define SMSTAGE (SMA + SMB)        // 32 KB
#define SMTOTAL (NSTAGE * SMSTAGE + 1024)

template<int EPI>
__global__ void __launch_bounds__(256, 2)
gemm_bf16x3(const __nv_bfloat16* __restrict__ Ah, const __nv_bfloat16* __restrict__ Al,
            const __nv_bfloat16* __restrict__ Bh, const __nv_bfloat16* __restrict__ Bl,
            float* __restrict__ C,
            __nv_bfloat16* __restrict__ Oh, __nv_bfloat16* __restrict__ Ol,
            const float* __restrict__ bias, const float* __restrict__ rt,
            const float* __restrict__ S, const int* __restrict__ root_idx,
            float* __restrict__ h1root)
{
    constexpr int K = 512;
    extern __shared__ char dsm[];
    uint32_t sb = (smem_u32(dsm) + 1023) & ~1023u;

    const int tid  = threadIdx.x;
    const int lane = tid & 31;
    const int wid  = tid >> 5;
    const int wm   = wid & 3;          // 4 warps along M (32 rows each)
    const int wn   = wid >> 2;         // 2 warps along N (64 cols each)
    const long bm  = (long)blockIdx.y * BM2;
    const long bn  = (long)blockIdx.x * BN2;

    const __nv_bfloat16* Aseg[3] = {Ah, Ah, Al};
    const __nv_bfloat16* Bseg[3] = {Bh, Bl, Bh};
    const int cps = K >> 6;            // 8
    const int nch = 3 * cps;           // 24

    float c[2][8][4];
#pragma unroll
    for (int i = 0; i < 2; i++)
#pragma unroll
        for (int j = 0; j < 8; j++)
#pragma unroll
            for (int q = 0; q < 4; q++) c[i][j][q] = 0.0f;

    const int amat  = lane >> 3;
    const int arow0 = wm * 32 + (amat & 1) * 8 + (lane & 7);
    const int ahalf = amat >> 1;
    const int bg    = lane >> 3;
    const int bhalf = bg & 1;
    const int bn0   = wn * 64 + ((bg >> 1) << 3) + (lane & 7);

    auto loads = [&](int ch, int s) {
        int seg = (ch >= 2 * cps) ? 2 : ((ch >= cps) ? 1 : 0);
        int kk  = (ch - seg * cps) << 6;
        const __nv_bfloat16* Ab = Aseg[seg] + bm * K + kk;
        const __nv_bfloat16* Bb = Bseg[seg] + bn * K + kk;
        uint32_t As = sb + s * SMSTAGE;
        uint32_t Bs = As + SMA;
#pragma unroll
        for (int i = 0; i < 4; i++) {              // A: 128 rows x 8 16B-chunks
            int lin = tid * 4 + i;
            int r = lin >> 3, cc = lin & 7;
            cp_async16(As + r * 128 + ((cc ^ (r & 7)) << 4), Ab + (long)r * K + cc * 8);
        }
#pragma unroll
        for (int i = 0; i < 4; i++) {              // B: 128 rows x 8 16B-chunks
            int lin = tid * 4 + i;
            int r = lin >> 3, cc = lin & 7;
            cp_async16(Bs + r * 128 + ((cc ^ (r & 7)) << 4), Bb + (long)r * K + cc * 8);
        }
    };

    loads(0, 0); cp_commit();
    loads(1, 1); cp_commit();

    int st = 0;                    // current stage index (mod 3)
    for (int k = 0; k < nch; k++) {
        cp_wait<1>();
        __syncthreads();
        if (k + 2 < nch) {
            int ps = st + 2; if (ps >= NSTAGE) ps -= NSTAGE;
            loads(k + 2, ps);
        }
        cp_commit();

        uint32_t As = sb + st * SMSTAGE;
        uint32_t Bs = As + SMA;
#pragma unroll
        for (int t = 0; t < 4; t++) {
            uint32_t a[2][4];
#pragma unroll
            for (int mi = 0; mi < 2; mi++) {
                int row = arow0 + mi * 16;
                uint32_t addr = As + row * 128 + ((((2 * t) + ahalf) ^ (row & 7)) << 4);
                ldsm_x4(a[mi][0], a[mi][1], a[mi][2], a[mi][3], addr);
            }
            uint32_t b[8][2];
#pragma unroll
            for (int j = 0; j < 4; j++) {
                int n = bn0 + j * 16;
                uint32_t addr = Bs + n * 128 + ((((2 * t) + bhalf) ^ (n & 7)) << 4);
                ldsm_x4(b[2 * j][0], b[2 * j][1], b[2 * j + 1][0], b[2 * j + 1][1], addr);
            }
#pragma unroll
            for (int mi = 0; mi < 2; mi++)
#pragma unroll
                for (int nj = 0; nj < 8; nj++)
                    mma16816(c[mi][nj], a[mi], b[nj]);
        }
        if (++st == NSTAGE) st = 0;
    }

#pragma unroll
    for (int mi = 0; mi < 2; mi++) {
        long row = bm + wm * 32 + mi * 16 + (lane >> 2);
        int g = (int)(row >> GSHIFT);
#pragma unroll
        for (int nj = 0; nj < 8; nj++) {
            int col = (int)bn + wn * 64 + nj * 8 + 2 * (lane & 3);
            float2 v0 = {c[mi][nj][0], c[mi][nj][1]};   // row
            float2 v1 = {c[mi][nj][2], c[mi][nj][3]};   // row + 8

            if (EPI == 3) {
                float b0 = bias[col], b1v = bias[col + 1];
                v0.x += b0; v0.y += b1v; v1.x += b0; v1.y += b1v;
                int rr = root_idx[g];
                if ((long)rr == row) {
                    h1root[g * 512 + col] = v0.x; h1root[g * 512 + col + 1] = v0.y;
                }
                if ((long)rr == row + 8) {
                    h1root[g * 512 + col] = v1.x; h1root[g * 512 + col + 1] = v1.y;
                }
                v0.x = fmaxf(v0.x, 0.f); v0.y = fmaxf(v0.y, 0.f);
                v1.x = fmaxf(v1.x, 0.f); v1.y = fmaxf(v1.y, 0.f);
                split_store2(Oh + row * 512 + col,       Ol + row * 512 + col,       v0);
                split_store2(Oh + (row + 8) * 512 + col, Ol + (row + 8) * 512 + col, v1);
            } else if (EPI == 4) {
                float s0 = S[row], s1 = S[row + 8];
                float r0 = rt[g * 512 + col], r1 = rt[g * 512 + col + 1];
                float b0 = bias[col], b1v = bias[col + 1];
                v0.x += b0 + s0 * r0; v0.y += b1v + s0 * r1;
                v1.x += b0 + s1 * r0; v1.y += b1v + s1 * r1;
                v0.x = fmaxf(v0.x, 0.f); v0.y = fmaxf(v0.y, 0.f);
                v1.x = fmaxf(v1.x, 0.f); v1.y = fmaxf(v1.y, 0.f);
                split_store2(Oh + row * 512 + col,       Ol + row * 512 + col,       v0);
                split_store2(Oh + (row + 8) * 512 + col, Ol + (row + 8) * 512 + col, v1);
            } else {  // EPI == 2
                float b0 = rt[g * 512 + col], b1v = rt[g * 512 + col + 1];
                v0.x += b0; v0.y += b1v; v1.x += b0; v1.y += b1v;
                v0.x = (v0.x >= 0.f) ? v0.x : 0.01f * v0.x;
                v0.y = (v0.y >= 0.f) ? v0.y : 0.01f * v0.y;
                v1.x = (v1.x >= 0.f) ? v1.x : 0.01f * v1.x;
                v1.y = (v1.y >= 0.f) ? v1.y : 0.01f * v1.y;
                *(float2*)(C + row * 512 + col)       = v0;
                *(float2*)(C + (row + 8) * 512 + col) = v1;
            }
        }
    }
}

// ---------------------------------------------------------------------------
// fused: split+transpose W1/W2a/Wla to bf16 hi/lo AND zero the CSR histogram
// ---------------------------------------------------------------------------
__global__ void split_w_zero_kernel(const float* __restrict__ W1,
                                    const float* __restrict__ W2,
                                    const float* __restrict__ Wl,
                                    __nv_bfloat16* __restrict__ w1h, __nv_bfloat16* __restrict__ w1l,
                                    __nv_bfloat16* __restrict__ w2h, __nv_bfloat16* __restrict__ w2l,
                                    __nv_bfloat16* __restrict__ wlh, __nv_bfloat16* __restrict__ wll,
                                    int* __restrict__ cnt)
{
    long idx = (long)blockIdx.x * blockDim.x + threadIdx.x;
    if (idx < MROWS) cnt[idx] = 0;
    int which = (int)(idx >> 18);
    int loc   = (int)(idx & 0x3FFFF);
    int n = loc >> 9;
    int k = loc & 511;
    const float* W = (which == 0) ? W1 : (which == 1) ? W2 : Wl;
    __nv_bfloat16* wh = (which == 0) ? w1h : (which == 1) ? w2h : wlh;
    __nv_bfloat16* wl = (which == 0) ? w1l : (which == 1) ? w2l : wll;
    float x = __ldg(&W[(long)k * 512 + n]);
    __nv_bfloat16 h, l;
    split1(x, h, l);
    wh[loc] = h; wl[loc] = l;
}

// ---------------------------------------------------------------------------
// CSR build
// ---------------------------------------------------------------------------
__global__ void hist_kernel(const int* __restrict__ rows, int* __restrict__ cnt, int nE)
{
    int e = blockIdx.x * blockDim.x + threadIdx.x;
    if (e < nE) atomicAdd(&cnt[rows[e]], 1);
}
__global__ void __launch_bounds__(1024, 1)
scan_kernel(const int* __restrict__ cnt, int* __restrict__ offs, int* __restrict__ cursor)
{
    __shared__ int ts[1024];
    const int tid = threadIdx.x;
    const int base = tid * 64;
    int local = 0;
#pragma unroll 8
    for (int i = 0; i < 64; i++) local += cnt[base + i];
    int x = local;
    ts[tid] = x; __syncthreads();
    for (int s = 1; s < 1024; s <<= 1) {
        int v = (tid >= s) ? ts[tid - s] : 0;
        __syncthreads();
        x += v; ts[tid] = x; __syncthreads();
    }
    int run = x - local;
    for (int i = 0; i < 64; i++) {
        int cc = cnt[base + i];
        offs[base + i] = run;
        cursor[base + i] = run;
        run += cc;
    }
    if (tid == 1023) offs[MROWS] = run;
}
__global__ void fill_csr_kernel(const int* __restrict__ rows, const int* __restrict__ cols,
                                const float* __restrict__ vals, int* __restrict__ cursor,
                                int* __restrict__ ecol, float* __restrict__ ew, int nE)
{
    int e = blockIdx.x * blockDim.x + threadIdx.x;
    if (e >= nE) return;
    int p = atomicAdd(&cursor[rows[e]], 1);
    ecol[p] = cols[e];
    ew[p]   = vals[e];
}

// ---------------------------------------------------------------------------
// CSR gathers (one 128-thread block per destination row), 4-edge batching
// ---------------------------------------------------------------------------
__global__ void __launch_bounds__(128)
gather_f32_kernel(const float* __restrict__ src, const int* __restrict__ offs,
                  const int* __restrict__ ecol, const float* __restrict__ ew,
                  __nv_bfloat16* __restrict__ oh, __nv_bfloat16* __restrict__ ol,
                  float* __restrict__ S)
{
    const int r = blockIdx.x;
    const int tid = threadIdx.x;
    const int beg = __ldg(&offs[r]), end = __ldg(&offs[r + 1]);
    float4 acc = make_float4(0.f, 0.f, 0.f, 0.f);
    float s = 0.f;
    int i = beg;
    for (; i + 4 <= end; i += 4) {
        int c0 = __ldg(&ecol[i]),   c1 = __ldg(&ecol[i+1]);
        int c2 = __ldg(&ecol[i+2]), c3 = __ldg(&ecol[i+3]);
        float w0 = __ldg(&ew[i]),   w1 = __ldg(&ew[i+1]);
        float w2 = __ldg(&ew[i+2]), w3 = __ldg(&ew[i+3]);
        float4 v0 = __ldg((const float4*)(src + (long)c0 * 512) + tid);
        float4 v1 = __ldg((const float4*)(src + (long)c1 * 512) + tid);
        float4 v2 = __ldg((const float4*)(src + (long)c2 * 512) + tid);
        float4 v3 = __ldg((const float4*)(src + (long)c3 * 512) + tid);
        acc.x += w0*v0.x + w1*v1.x + w2*v2.x + w3*v3.x;
        acc.y += w0*v0.y + w1*v1.y + w2*v2.y + w3*v3.y;
        acc.z += w0*v0.z + w1*v1.z + w2*v2.z + w3*v3.z;
        acc.w += w0*v0.w + w1*v1.w + w2*v2.w + w3*v3.w;
        s += w0 + w1 + w2 + w3;
    }
    for (; i < end; i++) {
        int cc = __ldg(&ecol[i]);
        float w = __ldg(&ew[i]);
        float4 v = __ldg((const float4*)(src + (long)cc * 512) + tid);
        acc.x += w * v.x; acc.y += w * v.y; acc.z += w * v.z; acc.w += w * v.w;
        s += w;
    }
    if (tid == 0) S[r] = s;
    split_store4(oh + (long)r * 512 + tid * 4, ol + (long)r * 512 + tid * 4, acc);
}

__device__ __forceinline__ float4 ld_bf16pair(const __nv_bfloat16* sh,
                                              const __nv_bfloat16* sl,
                                              long row, int tid)
{
    const __nv_bfloat162* ph = (const __nv_bfloat162*)(sh + row * 512) + tid * 2;
    const __nv_bfloat162* pl = (const __nv_bfloat162*)(sl + row * 512) + tid * 2;
    __nv_bfloat162 h0 = __ldg(ph), h1 = __ldg(ph + 1);
    __nv_bfloat162 l0 = __ldg(pl), l1 = __ldg(pl + 1);
    float4 v;
    v.x = __bfloat162float(h0.x) + __bfloat162float(l0.x);
    v.y = __bfloat162float(h0.y) + __bfloat162float(l0.y);
    v.z = __bfloat162float(h1.x) + __bfloat162float(l1.x);
    v.w = __bfloat162float(h1.y) + __bfloat162float(l1.y);
    return v;
}

__global__ void __launch_bounds__(128)
gather_bf16_kernel(const __nv_bfloat16* __restrict__ sh, const __nv_bfloat16* __restrict__ sl,
                   const int* __restrict__ offs, const int* __restrict__ ecol,
                   const float* __restrict__ ew,
                   __nv_bfloat16* __restrict__ oh, __nv_bfloat16* __restrict__ ol)
{
    const int r = blockIdx.x;
    const int tid = threadIdx.x;
    const int beg = __ldg(&offs[r]), end = __ldg(&offs[r + 1]);
    float4 acc = make_float4(0.f, 0.f, 0.f, 0.f);
    int i = beg;
    for (; i + 4 <= end; i += 4) {
        int c0 = __ldg(&ecol[i]),   c1 = __ldg(&ecol[i+1]);
        int c2 = __ldg(&ecol[i+2]), c3 = __ldg(&ecol[i+3]);
        float w0 = __ldg(&ew[i]),   w1 = __ldg(&ew[i+1]);
        float w2 = __ldg(&ew[i+2]), w3 = __ldg(&ew[i+3]);
        float4 v0 = ld_bf16pair(sh, sl, c0, tid);
        float4 v1 = ld_bf16pair(sh, sl, c1, tid);
        float4 v2 = ld_bf16pair(sh, sl, c2, tid);
        float4 v3 = ld_bf16pair(sh, sl, c3, tid);
        acc.x += w0*v0.x + w1*v1.x + w2*v2.x + w3*v3.x;
        acc.y += w0*v0.y + w1*v1.y + w2*v2.y + w3*v3.y;
        acc.z += w0*v0.z + w1*v1.z + w2*v2.z + w3*v3.z;
        acc.w += w0*v0.w + w1*v1.w + w2*v2.w + w3*v3.w;
    }
    for (; i < end; i++) {
        int cc = __ldg(&ecol[i]);
        float w = __ldg(&ew[i]);
        float4 v = ld_bf16pair(sh, sl, cc, tid);
        acc.x += w * v.x; acc.y += w * v.y; acc.z += w * v.z; acc.w += w * v.w;
    }
    split_store4(oh + (long)r * 512 + tid * 4, ol + (long)r * 512 + tid * 4, acc);
}

// ---------------------------------------------------------------------------
// root terms
// ---------------------------------------------------------------------------
__global__ void init_rt_kernel(float* __restrict__ rt, float* __restrict__ rt2,
                               const float* __restrict__ bl)
{
    int idx = blockIdx.x * blockDim.x + threadIdx.x;
    if (idx >= NGRAPH * DFEAT) return;
    rt[idx] = 0.f;
    rt2[idx] = bl[idx & 511];
}
__global__ void __launch_bounds__(512)
root_term_kernel(const float* __restrict__ feat, const int* __restrict__ root_idx,
                 const float* __restrict__ W2, float* __restrict__ rt)
{
    int g  = blockIdx.x;
    int kc = blockIdx.y << 6;
    int n  = threadIdx.x;
    const float* v  = feat + (long)root_idx[g] * DFEAT + kc;
    const float* Wb = W2 + (long)(512 + kc) * 512 + n;
    float acc = 0.f;
#pragma unroll 8
    for (int k = 0; k < 64; k++)
        acc += fmaxf(__ldg(v + k), 0.f) * __ldg(Wb + (long)k * 512);
    atomicAdd(&rt[g * DFEAT + n], acc);
}
__global__ void __launch_bounds__(512)
root_term2_kernel(const float* __restrict__ h1root, const float* __restrict__ Wl,
                  float* __restrict__ rt2)
{
    int g  = blockIdx.x;
    int kc = blockIdx.y << 6;
    int n  = threadIdx.x;
    const float* v  = h1root + g * DFEAT + kc;
    const float* Wb = Wl + (long)(512 + kc) * 512 + n;
    float acc = 0.f;
#pragma unroll 8
    for (int k = 0; k < 64; k++)
        acc += __ldg(v + k) * __ldg(Wb + (long)k * 512);
    atomicAdd(&rt2[g * DFEAT + n], acc);
}

// ---------------------------------------------------------------------------
// launch
// ---------------------------------------------------------------------------
extern "C" void kernel_launch(void* const* d_in, const int* in_sizes, int n_in,
                              void* d_out, int out_size)
{
    const float* features = (const float*)d_in[0];
    const int*   adjs     = (const int*)  d_in[1];
    const float* values   = (const float*)d_in[2];
    const int*   root_idx = (const int*)  d_in[3];
    const float* W1 = (const float*)d_in[6];
    const float* b1 = (const float*)d_in[7];
    const float* W2 = (const float*)d_in[8];
    const float* b2 = (const float*)d_in[9];
    const float* Wl = (const float*)d_in[10];
    const float* bl = (const float*)d_in[11];
    float* out = (float*)d_out;

    const int nE = in_sizes[2];

    float *S, *rt, *rt2, *h1root, *ew;
    int *cnt, *offs, *cursor, *ecol;
    __nv_bfloat16 *ah, *al, *bh, *blo, *w1h, *w1l, *w2h, *w2l, *wlh, *wll;
    cudaGetSymbolAddress((void**)&S,      g_S);
    cudaGetSymbolAddress((void**)&rt,     g_rt);
    cudaGetSymbolAddress((void**)&rt2,    g_rt2);
    cudaGetSymbolAddress((void**)&h1root, g_h1root);
    cudaGetSymbolAddress((void**)&cnt,    g_cnt);
    cudaGetSymbolAddress((void**)&offs,   g_offs);
    cudaGetSymbolAddress((void**)&cursor, g_cursor);
    cudaGetSymbolAddress((void**)&ecol,   g_ecol);
    cudaGetSymbolAddress((void**)&ew,     g_ew);
    cudaGetSymbolAddress((void**)&ah,  g_ah);
    cudaGetSymbolAddress((void**)&al,  g_al);
    cudaGetSymbolAddress((void**)&bh,  g_bh);
    cudaGetSymbolAddress((void**)&blo, g_bl);
    cudaGetSymbolAddress((void**)&w1h, g_w1h);
    cudaGetSymbolAddress((void**)&w1l, g_w1l);
    cudaGetSymbolAddress((void**)&w2h, g_w2h);
    cudaGetSymbolAddress((void**)&w2l, g_w2l);
    cudaGetSymbolAddress((void**)&wlh, g_wlh);
    cudaGetSymbolAddress((void**)&wll, g_wll);

    const int* rows = adjs;
    const int* cols = adjs + nE;

    cudaFuncSetAttribute(gemm_bf16x3<3>, cudaFuncAttributeMaxDynamicSharedMemorySize, SMTOTAL);
    cudaFuncSetAttribute(gemm_bf16x3<4>, cudaFuncAttributeMaxDynamicSharedMemorySize, SMTOTAL);
    cudaFuncSetAttribute(gemm_bf16x3<2>, cudaFuncAttributeMaxDynamicSharedMemorySize, SMTOTAL);

    dim3 ggrid(DFEAT / BN2, MROWS / BM2);             // (4, 512)
    dim3 rtg(NGRAPH, 8);

    // #0: weight split + cnt zero
    split_w_zero_kernel<<<(3 * 512 * 512 + 255) / 256, 256>>>(
        W1, W2, Wl, w1h, w1l, w2h, w2l, wlh, wll, cnt);
    // #1-3: CSR build
    hist_kernel<<<(nE + 255) / 256, 256>>>(rows, cnt, nE);
    scan_kernel<<<1, 1024>>>(cnt, offs, cursor);
    fill_csr_kernel<<<(nE + 255) / 256, 256>>>(rows, cols, values, cursor, ecol, ew, nE);
    // #4: PX = P @ X (split bf16) + S
    gather_f32_kernel<<<MROWS, 128>>>(features, offs, ecol, ew, ah, al, S);
    // #5: h1 = PX @ W1 + b1 (root-store, relu, split) -> bh/blo
    gemm_bf16x3<3><<<ggrid, 256, SMTOTAL>>>(ah, al, w1h, w1l, nullptr,
                                            bh, blo, b1, nullptr, nullptr, root_idx, h1root);
    // #6-8: root terms
    init_rt_kernel<<<(NGRAPH * DFEAT + 255) / 256, 256>>>(rt, rt2, bl);
    root_term_kernel<<<rtg, 512>>>(features, root_idx, W2, rt);
    root_term2_kernel<<<rtg, 512>>>(h1root, Wl, rt2);
    // #9: Y = P @ relu(h1) (split bf16) -> ah/al
    gather_bf16_kernel<<<MROWS, 128>>>(bh, blo, offs, ecol, ew, ah, al);
    // #10: h2 = Y @ W2a + b2 + S*rt[g] (relu, split) -> bh/blo
    gemm_bf16x3<4><<<ggrid, 256, SMTOTAL>>>(ah, al, w2h, w2l, nullptr,
                                            bh, blo, b2, rt, S, nullptr, nullptr);
    // #11: out = leaky_relu(relu(h2) @ Wla + rt2[g])
    gemm_bf16x3<2><<<ggrid, 256, SMTOTAL>>>(bh, blo, wlh, wll, out,
                                            nullptr, nullptr, nullptr, rt2, nullptr, nullptr, nullptr);
}

// round 9
// speedup vs baseline: 1.3120x; 1.0680x over previous
#include <cuda_runtime.h>
#include <cuda_bf16.h>
#include <cstdint>

#define MROWS   65536
#define DFEAT   512
#define NEDGES  65536
#define NGRAPH  16
#define GSHIFT  12          // rows per graph = 4096

// ---------------------------------------------------------------------------
// Scratch (__device__ globals; allocation-free)
// ---------------------------------------------------------------------------
__device__ float g_S[MROWS];
__device__ float g_rt[NGRAPH * DFEAT];
__device__ float g_rt2[NGRAPH * DFEAT];
__device__ float g_h1root[NGRAPH * DFEAT];
__device__ __nv_bfloat16 g_ah[(size_t)MROWS * DFEAT], g_al[(size_t)MROWS * DFEAT];
__device__ __nv_bfloat16 g_bh[(size_t)MROWS * DFEAT], g_bl[(size_t)MROWS * DFEAT];
__device__ __nv_bfloat16 g_w1h[512 * 512], g_w1l[512 * 512];
__device__ __nv_bfloat16 g_w2h[512 * 512], g_w2l[512 * 512];
__device__ __nv_bfloat16 g_wlh[512 * 512], g_wll[512 * 512];
// CSR
__device__ int   g_cnt[MROWS];
__device__ int   g_offs[MROWS + 1];
__device__ int   g_cursor[MROWS];
__device__ int   g_ecol[NEDGES];
__device__ float g_ew[NEDGES];

// ---------------------------------------------------------------------------
// PTX helpers
// ---------------------------------------------------------------------------
__device__ __forceinline__ uint32_t smem_u32(const void* p) {
    return (uint32_t)__cvta_generic_to_shared(p);
}
__device__ __forceinline__ void cp_async16(uint32_t dst, const void* src) {
    asm volatile("cp.async.cg.shared.global [%0], [%1], 16;" :: "r"(dst), "l"(src));
}
__device__ __forceinline__ void cp_commit() {
    asm volatile("cp.async.commit_group;");
}
template<int N>
__device__ __forceinline__ void cp_wait() {
    asm volatile("cp.async.wait_group %0;" :: "n"(N));
}
__device__ __forceinline__ void ldsm_x4(uint32_t& r0, uint32_t& r1,
                                        uint32_t& r2, uint32_t& r3, uint32_t a) {
    asm volatile("ldmatrix.sync.aligned.m8n8.x4.shared.b16 {%0,%1,%2,%3}, [%4];"
                 : "=r"(r0), "=r"(r1), "=r"(r2), "=r"(r3) : "r"(a));
}
__device__ __forceinline__ void mma16816(float* c, const uint32_t* a, const uint32_t* b) {
    asm volatile(
        "mma.sync.aligned.m16n8k16.row.col.f32.bf16.bf16.f32 "
        "{%0,%1,%2,%3}, {%4,%5,%6,%7}, {%8,%9}, {%0,%1,%2,%3};"
        : "+f"(c[0]), "+f"(c[1]), "+f"(c[2]), "+f"(c[3])
        : "r"(a[0]), "r"(a[1]), "r"(a[2]), "r"(a[3]), "r"(b[0]), "r"(b[1]));
}

// ---------------------------------------------------------------------------
// split helpers
// ---------------------------------------------------------------------------
__device__ __forceinline__ void split1(float x, __nv_bfloat16& h, __nv_bfloat16& l) {
    h = __float2bfloat16_rn(x);
    l = __float2bfloat16_rn(x - __bfloat162float(h));
}
__device__ __forceinline__ void split_store2(__nv_bfloat16* ph, __nv_bfloat16* pl, float2 v) {
    __nv_bfloat16 h0, l0, h1, l1;
    split1(v.x, h0, l0); split1(v.y, h1, l1);
    __nv_bfloat162 hh, ll;
    hh.x = h0; hh.y = h1; ll.x = l0; ll.y = l1;
    *(__nv_bfloat162*)ph = hh; *(__nv_bfloat162*)pl = ll;
}
__device__ __forceinline__ void split_store4(__nv_bfloat16* ph, __nv_bfloat16* pl, float4 v) {
    split_store2(ph,     pl,     make_float2(v.x, v.y));
    split_store2(ph + 2, pl + 2, make_float2(v.z, v.w));
}

// ---------------------------------------------------------------------------
// bf16x3 split GEMM: C = (Ah+Al)[M,512] @ (Bh+Bl)[512,512]^T
// CTA 128x128, 512 threads, 16 warps of 32x32, BK=64, 3-stage cp.async,
// 2 CTAs/SM => 32 warps/SM.
// EPI=3: +bias(col); fp32 root-row store; relu; split->Oh/Ol
// EPI=4: +bias(col)+S[row]*rt[g,col]; relu; split->Oh/Ol
// EPI=2: +rt2[g,col]; leaky_relu; fp32 store -> C
// ---------------------------------------------------------------------------
#define BM2 128
#define BN2 128
#define NSTAGE 3
#define SMA (BM2 * 128)            // 16 KB
#define SMB (BN2 * 128)            // 16 KB
#define SMSTAGE (SMA + SMB)        // 32 KB
#define SMTOTAL (NSTAGE * SMSTAGE + 1024)

template<int EPI>
__global__ void __launch_bounds__(512, 2)
gemm_bf16x3(const __nv_bfloat16* __restrict__ Ah, const __nv_bfloat16* __restrict__ Al,
            const __nv_bfloat16* __restrict__ Bh, const __nv_bfloat16* __restrict__ Bl,
            float* __restrict__ C,
            __nv_bfloat16* __restrict__ Oh, __nv_bfloat16* __restrict__ Ol,
            const float* __restrict__ bias, const float* __restrict__ rt,
            const float* __restrict__ S, const int* __restrict__ root_idx,
            float* __restrict__ h1root)
{
    constexpr int K = 512;
    extern __shared__ char dsm[];
    uint32_t sb = (smem_u32(dsm) + 1023) & ~1023u;

    const int tid  = threadIdx.x;
    const int lane = tid & 31;
    const int wid  = tid >> 5;
    const int wm   = wid & 3;          // 4 warp-rows (32 M each)
    const int wn   = wid >> 2;         // 4 warp-cols (32 N each)
    const long bm  = (long)blockIdx.y * BM2;
    const long bn  = (long)blockIdx.x * BN2;

    const __nv_bfloat16* Aseg[3] = {Ah, Ah, Al};
    const __nv_bfloat16* Bseg[3] = {Bh, Bl, Bh};
    const int cps = K >> 6;            // 8
    const int nch = 3 * cps;           // 24

    float c[2][4][4];
#pragma unroll
    for (int i = 0; i < 2; i++)
#pragma unroll
        for (int j = 0; j < 4; j++)
#pragma unroll
            for (int q = 0; q < 4; q++) c[i][j][q] = 0.0f;

    const int amat  = lane >> 3;
    const int arow0 = wm * 32 + (amat & 1) * 8 + (lane & 7);
    const int ahalf = amat >> 1;
    const int bg    = lane >> 3;
    const int bhalf = bg & 1;
    const int bn0   = wn * 32 + ((bg >> 1) << 3) + (lane & 7);

    auto loads = [&](int ch, int s) {
        int seg = (ch >= 2 * cps) ? 2 : ((ch >= cps) ? 1 : 0);
        int kk  = (ch - seg * cps) << 6;
        const __nv_bfloat16* Ab = Aseg[seg] + bm * K + kk;
        const __nv_bfloat16* Bb = Bseg[seg] + bn * K + kk;
        uint32_t As = sb + s * SMSTAGE;
        uint32_t Bs = As + SMA;
#pragma unroll
        for (int i = 0; i < 2; i++) {              // A: 128 rows x 8 16B-chunks
            int lin = tid * 2 + i;
            int r = lin >> 3, cc = lin & 7;
            cp_async16(As + r * 128 + ((cc ^ (r & 7)) << 4), Ab + (long)r * K + cc * 8);
        }
#pragma unroll
        for (int i = 0; i < 2; i++) {              // B: 128 rows x 8 16B-chunks
            int lin = tid * 2 + i;
            int r = lin >> 3, cc = lin & 7;
            cp_async16(Bs + r * 128 + ((cc ^ (r & 7)) << 4), Bb + (long)r * K + cc * 8);
        }
    };

    loads(0, 0); cp_commit();
    loads(1, 1); cp_commit();

    int st = 0;
    for (int k = 0; k < nch; k++) {
        cp_wait<1>();
        __syncthreads();
        if (k + 2 < nch) {
            int ps = st + 2; if (ps >= NSTAGE) ps -= NSTAGE;
            loads(k + 2, ps);
        }
        cp_commit();

        uint32_t As = sb + st * SMSTAGE;
        uint32_t Bs = As + SMA;
#pragma unroll
        for (int t = 0; t < 4; t++) {
            uint32_t a[2][4];
#pragma unroll
            for (int mi = 0; mi < 2; mi++) {
                int row = arow0 + mi * 16;
                uint32_t addr = As + row * 128 + ((((2 * t) + ahalf) ^ (row & 7)) << 4);
                ldsm_x4(a[mi][0], a[mi][1], a[mi][2], a[mi][3], addr);
            }
            uint32_t b[4][2];
#pragma unroll
            for (int j = 0; j < 2; j++) {
                int n = bn0 + j * 16;
                uint32_t addr = Bs + n * 128 + ((((2 * t) + bhalf) ^ (n & 7)) << 4);
                ldsm_x4(b[2 * j][0], b[2 * j][1], b[2 * j + 1][0], b[2 * j + 1][1], addr);
            }
#pragma unroll
            for (int mi = 0; mi < 2; mi++)
#pragma unroll
                for (int nj = 0; nj < 4; nj++)
                    mma16816(c[mi][nj], a[mi], b[nj]);
        }
        if (++st == NSTAGE) st = 0;
    }

#pragma unroll
    for (int mi = 0; mi < 2; mi++) {
        long row = bm + wm * 32 + mi * 16 + (lane >> 2);
        int g = (int)(row >> GSHIFT);
#pragma unroll
        for (int nj = 0; nj < 4; nj++) {
            int col = (int)bn + wn * 32 + nj * 8 + 2 * (lane & 3);
            float2 v0 = {c[mi][nj][0], c[mi][nj][1]};   // row
            float2 v1 = {c[mi][nj][2], c[mi][nj][3]};   // row + 8

            if (EPI == 3) {
                float b0 = bias[col], b1v = bias[col + 1];
                v0.x += b0; v0.y += b1v; v1.x += b0; v1.y += b1v;
                int rr = root_idx[g];
                if ((long)rr == row) {
                    h1root[g * 512 + col] = v0.x; h1root[g * 512 + col + 1] = v0.y;
                }
                if ((long)rr == row + 8) {
                    h1root[g * 512 + col] = v1.x; h1root[g * 512 + col + 1] = v1.y;
                }
                v0.x = fmaxf(v0.x, 0.f); v0.y = fmaxf(v0.y, 0.f);
                v1.x = fmaxf(v1.x, 0.f); v1.y = fmaxf(v1.y, 0.f);
                split_store2(Oh + row * 512 + col,       Ol + row * 512 + col,       v0);
                split_store2(Oh + (row + 8) * 512 + col, Ol + (row + 8) * 512 + col, v1);
            } else if (EPI == 4) {
                float s0 = S[row], s1 = S[row + 8];
                float r0 = rt[g * 512 + col], r1 = rt[g * 512 + col + 1];
                float b0 = bias[col], b1v = bias[col + 1];
                v0.x += b0 + s0 * r0; v0.y += b1v + s0 * r1;
                v1.x += b0 + s1 * r0; v1.y += b1v + s1 * r1;
                v0.x = fmaxf(v0.x, 0.f); v0.y = fmaxf(v0.y, 0.f);
                v1.x = fmaxf(v1.x, 0.f); v1.y = fmaxf(v1.y, 0.f);
                split_store2(Oh + row * 512 + col,       Ol + row * 512 + col,       v0);
                split_store2(Oh + (row + 8) * 512 + col, Ol + (row + 8) * 512 + col, v1);
            } else {  // EPI == 2
                float b0 = rt[g * 512 + col], b1v = rt[g * 512 + col + 1];
                v0.x += b0; v0.y += b1v; v1.x += b0; v1.y += b1v;
                v0.x = (v0.x >= 0.f) ? v0.x : 0.01f * v0.x;
                v0.y = (v0.y >= 0.f) ? v0.y : 0.01f * v0.y;
                v1.x = (v1.x >= 0.f) ? v1.x : 0.01f * v1.x;
                v1.y = (v1.y >= 0.f) ? v1.y : 0.01f * v1.y;
                *(float2*)(C + row * 512 + col)       = v0;
                *(float2*)(C + (row + 8) * 512 + col) = v1;
            }
        }
    }
}

// ---------------------------------------------------------------------------
// fused: split+transpose W1/W2a/Wla to bf16 hi/lo AND zero the CSR histogram
// ---------------------------------------------------------------------------
__global__ void split_w_zero_kernel(const float* __restrict__ W1,
                                    const float* __restrict__ W2,
                                    const float* __restrict__ Wl,
                                    __nv_bfloat16* __restrict__ w1h, __nv_bfloat16* __restrict__ w1l,
                                    __nv_bfloat16* __restrict__ w2h, __nv_bfloat16* __restrict__ w2l,
                                    __nv_bfloat16* __restrict__ wlh, __nv_bfloat16* __restrict__ wll,
                                    int* __restrict__ cnt)
{
    long idx = (long)blockIdx.x * blockDim.x + threadIdx.x;
    if (idx < MROWS) cnt[idx] = 0;
    if (idx >= 3 * 512 * 512) return;
    int which = (int)(idx >> 18);
    int loc   = (int)(idx & 0x3FFFF);
    int n = loc >> 9;
    int k = loc & 511;
    const float* W = (which == 0) ? W1 : (which == 1) ? W2 : Wl;
    __nv_bfloat16* wh = (which == 0) ? w1h : (which == 1) ? w2h : wlh;
    __nv_bfloat16* wl = (which == 0) ? w1l : (which == 1) ? w2l : wll;
    float x = __ldg(&W[(long)k * 512 + n]);
    __nv_bfloat16 h, l;
    split1(x, h, l);
    wh[loc] = h; wl[loc] = l;
}

// ---------------------------------------------------------------------------
// CSR build
// ---------------------------------------------------------------------------
__global__ void hist_kernel(const int* __restrict__ rows, int* __restrict__ cnt, int nE)
{
    int e = blockIdx.x * blockDim.x + threadIdx.x;
    if (e < nE) atomicAdd(&cnt[rows[e]], 1);
}
__global__ void __launch_bounds__(1024, 1)
scan_kernel(const int* __restrict__ cnt, int* __restrict__ offs, int* __restrict__ cursor)
{
    __shared__ int ts[1024];
    const int tid = threadIdx.x;
    const int base = tid * 64;
    int local = 0;
#pragma unroll 8
    for (int i = 0; i < 64; i++) local += cnt[base + i];
    int x = local;
    ts[tid] = x; __syncthreads();
    for (int s = 1; s < 1024; s <<= 1) {
        int v = (tid >= s) ? ts[tid - s] : 0;
        __syncthreads();
        x += v; ts[tid] = x; __syncthreads();
    }
    int run = x - local;
    for (int i = 0; i < 64; i++) {
        int cc = cnt[base + i];
        offs[base + i] = run;
        cursor[base + i] = run;
        run += cc;
    }
    if (tid == 1023) offs[MROWS] = run;
}
__global__ void fill_csr_kernel(const int* __restrict__ rows, const int* __restrict__ cols,
                                const float* __restrict__ vals, int* __restrict__ cursor,
                                int* __restrict__ ecol, float* __restrict__ ew, int nE)
{
    int e = blockIdx.x * blockDim.x + threadIdx.x;
    if (e >= nE) return;
    int p = atomicAdd(&cursor[rows[e]], 1);
    ecol[p] = cols[e];
    ew[p]   = vals[e];
}

// ---------------------------------------------------------------------------
// CSR gathers (one 128-thread block per destination row), 4-edge batching
// ---------------------------------------------------------------------------
__global__ void __launch_bounds__(128)
gather_f32_kernel(const float* __restrict__ src, const int* __restrict__ offs,
                  const int* __restrict__ ecol, const float* __restrict__ ew,
                  __nv_bfloat16* __restrict__ oh, __nv_bfloat16* __restrict__ ol,
                  float* __restrict__ S)
{
    const int r = blockIdx.x;
    const int tid = threadIdx.x;
    const int beg = __ldg(&offs[r]), end = __ldg(&offs[r + 1]);
    float4 acc = make_float4(0.f, 0.f, 0.f, 0.f);
    float s = 0.f;
    int i = beg;
    for (; i + 4 <= end; i += 4) {
        int c0 = __ldg(&ecol[i]),   c1 = __ldg(&ecol[i+1]);
        int c2 = __ldg(&ecol[i+2]), c3 = __ldg(&ecol[i+3]);
        float w0 = __ldg(&ew[i]),   w1 = __ldg(&ew[i+1]);
        float w2 = __ldg(&ew[i+2]), w3 = __ldg(&ew[i+3]);
        float4 v0 = __ldg((const float4*)(src + (long)c0 * 512) + tid);
        float4 v1 = __ldg((const float4*)(src + (long)c1 * 512) + tid);
        float4 v2 = __ldg((const float4*)(src + (long)c2 * 512) + tid);
        float4 v3 = __ldg((const float4*)(src + (long)c3 * 512) + tid);
        acc.x += w0*v0.x + w1*v1.x + w2*v2.x + w3*v3.x;
        acc.y += w0*v0.y + w1*v1.y + w2*v2.y + w3*v3.y;
        acc.z += w0*v0.z + w1*v1.z + w2*v2.z + w3*v3.z;
        acc.w += w0*v0.w + w1*v1.w + w2*v2.w + w3*v3.w;
        s += w0 + w1 + w2 + w3;
    }
    for (; i < end; i++) {
        int cc = __ldg(&ecol[i]);
        float w = __ldg(&ew[i]);
        float4 v = __ldg((const float4*)(src + (long)cc * 512) + tid);
        acc.x += w * v.x; acc.y += w * v.y; acc.z += w * v.z; acc.w += w * v.w;
        s += w;
    }
    if (tid == 0) S[r] = s;
    split_store4(oh + (long)r * 512 + tid * 4, ol + (long)r * 512 + tid * 4, acc);
}

__device__ __forceinline__ float4 ld_bf16pair(const __nv_bfloat16* sh,
                                              const __nv_bfloat16* sl,
                                              long row, int tid)
{
    const __nv_bfloat162* ph = (const __nv_bfloat162*)(sh + row * 512) + tid * 2;
    const __nv_bfloat162* pl = (const __nv_bfloat162*)(sl + row * 512) + tid * 2;
    __nv_bfloat162 h0 = __ldg(ph), h1 = __ldg(ph + 1);
    __nv_bfloat162 l0 = __ldg(pl), l1 = __ldg(pl + 1);
    float4 v;
    v.x = __bfloat162float(h0.x) + __bfloat162float(l0.x);
    v.y = __bfloat162float(h0.y) + __bfloat162float(l0.y);
    v.z = __bfloat162float(h1.x) + __bfloat162float(l1.x);
    v.w = __bfloat162float(h1.y) + __bfloat162float(l1.y);
    return v;
}

__global__ void __launch_bounds__(128)
gather_bf16_kernel(const __nv_bfloat16* __restrict__ sh, const __nv_bfloat16* __restrict__ sl,
                   const int* __restrict__ offs, const int* __restrict__ ecol,
                   const float* __restrict__ ew,
                   __nv_bfloat16* __restrict__ oh, __nv_bfloat16* __restrict__ ol)
{
    const int r = blockIdx.x;
    const int tid = threadIdx.x;
    const int beg = __ldg(&offs[r]), end = __ldg(&offs[r + 1]);
    float4 acc = make_float4(0.f, 0.f, 0.f, 0.f);
    int i = beg;
    for (; i + 4 <= end; i += 4) {
        int c0 = __ldg(&ecol[i]),   c1 = __ldg(&ecol[i+1]);
        int c2 = __ldg(&ecol[i+2]), c3 = __ldg(&ecol[i+3]);
        float w0 = __ldg(&ew[i]),   w1 = __ldg(&ew[i+1]);
        float w2 = __ldg(&ew[i+2]), w3 = __ldg(&ew[i+3]);
        float4 v0 = ld_bf16pair(sh, sl, c0, tid);
        float4 v1 = ld_bf16pair(sh, sl, c1, tid);
        float4 v2 = ld_bf16pair(sh, sl, c2, tid);
        float4 v3 = ld_bf16pair(sh, sl, c3, tid);
        acc.x += w0*v0.x + w1*v1.x + w2*v2.x + w3*v3.x;
        acc.y += w0*v0.y + w1*v1.y + w2*v2.y + w3*v3.y;
        acc.z += w0*v0.z + w1*v1.z + w2*v2.z + w3*v3.z;
        acc.w += w0*v0.w + w1*v1.w + w2*v2.w + w3*v3.w;
    }
    for (; i < end; i++) {
        int cc = __ldg(&ecol[i]);
        float w = __ldg(&ew[i]);
        float4 v = ld_bf16pair(sh, sl, cc, tid);
        acc.x += w * v.x; acc.y += w * v.y; acc.z += w * v.z; acc.w += w * v.w;
    }
    split_store4(oh + (long)r * 512 + tid * 4, ol + (long)r * 512 + tid * 4, acc);
}

// ---------------------------------------------------------------------------
// root terms
// ---------------------------------------------------------------------------
__global__ void init_rt_kernel(float* __restrict__ rt, float* __restrict__ rt2,
                               const float* __restrict__ bl)
{
    int idx = blockIdx.x * blockDim.x + threadIdx.x;
    if (idx >= NGRAPH * DFEAT) return;
    rt[idx] = 0.f;
    rt2[idx] = bl[idx & 511];
}
__global__ void __launch_bounds__(512)
root_term_kernel(const float* __restrict__ feat, const int* __restrict__ root_idx,
                 const float* __restrict__ W2, float* __restrict__ rt)
{
    int g  = blockIdx.x;
    int kc = blockIdx.y << 6;
    int n  = threadIdx.x;
    const float* v  = feat + (long)root_idx[g] * DFEAT + kc;
    const float* Wb = W2 + (long)(512 + kc) * 512 + n;
    float acc = 0.f;
#pragma unroll 8
    for (int k = 0; k < 64; k++)
        acc += fmaxf(__ldg(v + k), 0.f) * __ldg(Wb + (long)k * 512);
    atomicAdd(&rt[g * DFEAT + n], acc);
}
__global__ void __launch_bounds__(512)
root_term2_kernel(const float* __restrict__ h1root, const float* __restrict__ Wl,
                  float* __restrict__ rt2)
{
    int g  = blockIdx.x;
    int kc = blockIdx.y << 6;
    int n  = threadIdx.x;
    const float* v  = h1root + g * DFEAT + kc;
    const float* Wb = Wl + (long)(512 + kc) * 512 + n;
    float acc = 0.f;
#pragma unroll 8
    for (int k = 0; k < 64; k++)
        acc += __ldg(v + k) * __ldg(Wb + (long)k * 512);
    atomicAdd(&rt2[g * DFEAT + n], acc);
}

// ---------------------------------------------------------------------------
// launch
// ---------------------------------------------------------------------------
extern "C" void kernel_launch(void* const* d_in, const int* in_sizes, int n_in,
                              void* d_out, int out_size)
{
    const float* features = (const float*)d_in[0];
    const int*   adjs     = (const int*)  d_in[1];
    const float* values   = (const float*)d_in[2];
    const int*   root_idx = (const int*)  d_in[3];
    const float* W1 = (const float*)d_in[6];
    const float* b1 = (const float*)d_in[7];
    const float* W2 = (const float*)d_in[8];
    const float* b2 = (const float*)d_in[9];
    const float* Wl = (const float*)d_in[10];
    const float* bl = (const float*)d_in[11];
    float* out = (float*)d_out;

    const int nE = in_sizes[2];

    float *S, *rt, *rt2, *h1root, *ew;
    int *cnt, *offs, *cursor, *ecol;
    __nv_bfloat16 *ah, *al, *bh, *blo, *w1h, *w1l, *w2h, *w2l, *wlh, *wll;
    cudaGetSymbolAddress((void**)&S,      g_S);
    cudaGetSymbolAddress((void**)&rt,     g_rt);
    cudaGetSymbolAddress((void**)&rt2,    g_rt2);
    cudaGetSymbolAddress((void**)&h1root, g_h1root);
    cudaGetSymbolAddress((void**)&cnt,    g_cnt);
    cudaGetSymbolAddress((void**)&offs,   g_offs);
    cudaGetSymbolAddress((void**)&cursor, g_cursor);
    cudaGetSymbolAddress((void**)&ecol,   g_ecol);
    cudaGetSymbolAddress((void**)&ew,     g_ew);
    cudaGetSymbolAddress((void**)&ah,  g_ah);
    cudaGetSymbolAddress((void**)&al,  g_al);
    cudaGetSymbolAddress((void**)&bh,  g_bh);
    cudaGetSymbolAddress((void**)&blo, g_bl);
    cudaGetSymbolAddress((void**)&w1h, g_w1h);
    cudaGetSymbolAddress((void**)&w1l, g_w1l);
    cudaGetSymbolAddress((void**)&w2h, g_w2h);
    cudaGetSymbolAddress((void**)&w2l, g_w2l);
    cudaGetSymbolAddress((void**)&wlh, g_wlh);
    cudaGetSymbolAddress((void**)&wll, g_wll);

    const int* rows = adjs;
    const int* cols = adjs + nE;

    cudaFuncSetAttribute(gemm_bf16x3<3>, cudaFuncAttributeMaxDynamicSharedMemorySize, SMTOTAL);
    cudaFuncSetAttribute(gemm_bf16x3<4>, cudaFuncAttributeMaxDynamicSharedMemorySize, SMTOTAL);
    cudaFuncSetAttribute(gemm_bf16x3<2>, cudaFuncAttributeMaxDynamicSharedMemorySize, SMTOTAL);

    dim3 ggrid(DFEAT / BN2, MROWS / BM2);             // (4, 512)
    dim3 rtg(NGRAPH, 8);

    // #0: weight split + cnt zero
    split_w_zero_kernel<<<(3 * 512 * 512 + 255) / 256, 256>>>(
        W1, W2, Wl, w1h, w1l, w2h, w2l, wlh, wll, cnt);
    // #1-3: CSR build
    hist_kernel<<<(nE + 255) / 256, 256>>>(rows, cnt, nE);
    scan_kernel<<<1, 1024>>>(cnt, offs, cursor);
    fill_csr_kernel<<<(nE + 255) / 256, 256>>>(rows, cols, values, cursor, ecol, ew, nE);
    // #4: PX = P @ X (split bf16) + S
    gather_f32_kernel<<<MROWS, 128>>>(features, offs, ecol, ew, ah, al, S);
    // #5: h1 = PX @ W1 + b1 (root-store, relu, split) -> bh/blo
    gemm_bf16x3<3><<<ggrid, 512, SMTOTAL>>>(ah, al, w1h, w1l, nullptr,
                                            bh, blo, b1, nullptr, nullptr, root_idx, h1root);
    // #6-8: root terms
    init_rt_kernel<<<(NGRAPH * DFEAT + 255) / 256, 256>>>(rt, rt2, bl);
    root_term_kernel<<<rtg, 512>>>(features, root_idx, W2, rt);
    root_term2_kernel<<<rtg, 512>>>(h1root, Wl, rt2);
    // #9: Y = P @ relu(h1) (split bf16) -> ah/al
    gather_bf16_kernel<<<MROWS, 128>>>(bh, blo, offs, ecol, ew, ah, al);
    // #10: h2 = Y @ W2a + b2 + S*rt[g] (relu, split) -> bh/blo
    gemm_bf16x3<4><<<ggrid, 512, SMTOTAL>>>(ah, al, w2h, w2l, nullptr,
                                            bh, blo, b2, rt, S, nullptr, nullptr);
    // #11: out = leaky_relu(relu(h2) @ Wla + rt2[g])
    gemm_bf16x3<2><<<ggrid, 512, SMTOTAL>>>(bh, blo, wlh, wll, out,
                                            nullptr, nullptr, nullptr, rt2, nullptr, nullptr, nullptr);
}

// round 10
// speedup vs baseline: 1.3356x; 1.0180x over previous
#include <cuda_runtime.h>
#include <cuda_bf16.h>
#include <cstdint>

#define MROWS   65536
#define DFEAT   512
#define NEDGES  65536
#define NGRAPH  16
#define GSHIFT  12          // rows per graph = 4096

// ---------------------------------------------------------------------------
// Scratch (__device__ globals; allocation-free)
// ---------------------------------------------------------------------------
__device__ float g_S[MROWS];
__device__ float g_rt[NGRAPH * DFEAT];
__device__ float g_rt2[NGRAPH * DFEAT];
__device__ float g_h1root[NGRAPH * DFEAT];
__device__ __nv_bfloat16 g_ah[(size_t)MROWS * DFEAT], g_al[(size_t)MROWS * DFEAT];
__device__ __nv_bfloat16 g_bh[(size_t)MROWS * DFEAT], g_bl[(size_t)MROWS * DFEAT];
__device__ __nv_bfloat16 g_w1h[512 * 512], g_w1l[512 * 512];
__device__ __nv_bfloat16 g_w2h[512 * 512], g_w2l[512 * 512];
__device__ __nv_bfloat16 g_wlh[512 * 512], g_wll[512 * 512];
// CSR
__device__ int   g_cnt[MROWS];
__device__ int   g_offs[MROWS + 1];
__device__ int   g_cursor[MROWS];
__device__ int   g_ecol[NEDGES];
__device__ float g_ew[NEDGES];

// ---------------------------------------------------------------------------
// PTX helpers
// ---------------------------------------------------------------------------
__device__ __forceinline__ uint32_t smem_u32(const void* p) {
    return (uint32_t)__cvta_generic_to_shared(p);
}
__device__ __forceinline__ void cp_async16(uint32_t dst, const void* src) {
    asm volatile("cp.async.cg.shared.global [%0], [%1], 16;" :: "r"(dst), "l"(src));
}
__device__ __forceinline__ void cp_commit() {
    asm volatile("cp.async.commit_group;");
}
template<int N>
__device__ __forceinline__ void cp_wait() {
    asm volatile("cp.async.wait_group %0;" :: "n"(N));
}
__device__ __forceinline__ void ldsm_x4(uint32_t& r0, uint32_t& r1,
                                        uint32_t& r2, uint32_t& r3, uint32_t a) {
    asm volatile("ldmatrix.sync.aligned.m8n8.x4.shared.b16 {%0,%1,%2,%3}, [%4];"
                 : "=r"(r0), "=r"(r1), "=r"(r2), "=r"(r3) : "r"(a));
}
__device__ __forceinline__ void mma16816(float* c, const uint32_t* a, const uint32_t* b) {
    asm volatile(
        "mma.sync.aligned.m16n8k16.row.col.f32.bf16.bf16.f32 "
        "{%0,%1,%2,%3}, {%4,%5,%6,%7}, {%8,%9}, {%0,%1,%2,%3};"
        : "+f"(c[0]), "+f"(c[1]), "+f"(c[2]), "+f"(c[3])
        : "r"(a[0]), "r"(a[1]), "r"(a[2]), "r"(a[3]), "r"(b[0]), "r"(b[1]));
}

// ---------------------------------------------------------------------------
// split helpers
// ---------------------------------------------------------------------------
__device__ __forceinline__ void split1(float x, __nv_bfloat16& h, __nv_bfloat16& l) {
    h = __float2bfloat16_rn(x);
    l = __float2bfloat16_rn(x - __bfloat162float(h));
}
__device__ __forceinline__ void split_store2(__nv_bfloat16* ph, __nv_bfloat16* pl, float2 v) {
    __nv_bfloat16 h0, l0, h1, l1;
    split1(v.x, h0, l0); split1(v.y, h1, l1);
    __nv_bfloat162 hh, ll;
    hh.x = h0; hh.y = h1; ll.x = l0; ll.y = l1;
    *(__nv_bfloat162*)ph = hh; *(__nv_bfloat162*)pl = ll;
}
__device__ __forceinline__ void split_store4(__nv_bfloat16* ph, __nv_bfloat16* pl, float4 v) {
    split_store2(ph,     pl,     make_float2(v.x, v.y));
    split_store2(ph + 2, pl + 2, make_float2(v.z, v.w));
}

// ---------------------------------------------------------------------------
// bf16x3 FUSED-SEGMENT split GEMM:
//   C = Ah@Bh^T + Al@Bh^T + Ah@Bl^T   (Ah/Al [M,512], Bh/Bl [512,512] row=[n,k])
// Per K-chunk we stage Ah,Al,Bh,Bl together and issue all three MMA terms:
// ldsm:MMA cycle ratio = 1:2 (tensor-bound), 8 chunks, 2-stage pipeline.
// CTA 128x256, 512 threads, 16 warps of 32x64, 1 CTA/SM (192 KB smem).
// EPI=3: +bias(col); fp32 root-row store; relu; split->Oh/Ol
// EPI=4: +bias(col)+S[row]*rt[g,col]; relu; split->Oh/Ol
// EPI=2: +rt2[g,col]; leaky_relu; fp32 store -> C
// ---------------------------------------------------------------------------
#define BM2 128
#define BN2 256
#define NSTAGE 2
#define SM_AH (BM2 * 128)                 // 16 KB
#define SM_AL (BM2 * 128)                 // 16 KB
#define SM_BH (BN2 * 128)                 // 32 KB
#define SM_BL (BN2 * 128)                 // 32 KB
#define SMSTAGE (SM_AH + SM_AL + SM_BH + SM_BL)   // 96 KB
#define SMTOTAL (NSTAGE * SMSTAGE + 1024)         // ~193 KB

template<int EPI>
__global__ void __launch_bounds__(512, 1)
gemm_bf16x3(const __nv_bfloat16* __restrict__ Ah, const __nv_bfloat16* __restrict__ Al,
            const __nv_bfloat16* __restrict__ Bh, const __nv_bfloat16* __restrict__ Bl,
            float* __restrict__ C,
            __nv_bfloat16* __restrict__ Oh, __nv_bfloat16* __restrict__ Ol,
            const float* __restrict__ bias, const float* __restrict__ rt,
            const float* __restrict__ S, const int* __restrict__ root_idx,
            float* __restrict__ h1root)
{
    constexpr int K = 512;
    constexpr int NCH = K / 64;           // 8
    extern __shared__ char dsm[];
    uint32_t sb = (smem_u32(dsm) + 1023) & ~1023u;

    const int tid  = threadIdx.x;
    const int lane = tid & 31;
    const int wid  = tid >> 5;
    const int wm   = wid & 3;             // 4 warp-rows (32 M each)
    const int wn   = wid >> 2;            // 4 warp-cols (64 N each)
    const long bm  = (long)blockIdx.y * BM2;
    const long bn  = (long)blockIdx.x * BN2;

    float c[2][8][4];
#pragma unroll
    for (int i = 0; i < 2; i++)
#pragma unroll
        for (int j = 0; j < 8; j++)
#pragma unroll
            for (int q = 0; q < 4; q++) c[i][j][q] = 0.0f;

    const int amat  = lane >> 3;
    const int arow0 = wm * 32 + (amat & 1) * 8 + (lane & 7);
    const int ahalf = amat >> 1;
    const int bg    = lane >> 3;
    const int bhalf = bg & 1;
    const int bn0   = wn * 64 + ((bg >> 1) << 3) + (lane & 7);

    auto loads = [&](int ch, int s) {
        int kk = ch << 6;
        uint32_t base = sb + s * SMSTAGE;
        const __nv_bfloat16* Ahp = Ah + bm * K + kk;
        const __nv_bfloat16* Alp = Al + bm * K + kk;
        const __nv_bfloat16* Bhp = Bh + bn * K + kk;
        const __nv_bfloat16* Blp = Bl + bn * K + kk;
#pragma unroll
        for (int i = 0; i < 2; i++) {              // Ah + Al: 128 rows x 8 16B
            int lin = tid * 2 + i;
            int r = lin >> 3, cc = lin & 7;
            uint32_t off = r * 128 + ((cc ^ (r & 7)) << 4);
            const __nv_bfloat16* src = Ahp + (long)r * K + cc * 8;
            cp_async16(base + off, src);
            cp_async16(base + SM_AH + off, Alp + (long)r * K + cc * 8);
        }
#pragma unroll
        for (int i = 0; i < 4; i++) {              // Bh + Bl: 256 rows x 8 16B
            int lin = tid * 4 + i;
            int r = lin >> 3, cc = lin & 7;
            uint32_t off = r * 128 + ((cc ^ (r & 7)) << 4);
            cp_async16(base + SM_AH + SM_AL + off, Bhp + (long)r * K + cc * 8);
            cp_async16(base + SM_AH + SM_AL + SM_BH + off, Blp + (long)r * K + cc * 8);
        }
    };

    loads(0, 0); cp_commit();
    loads(1, 1); cp_commit();

    for (int k = 0; k < NCH; k++) {
        cp_wait<1>();
        __syncthreads();
        uint32_t As_h = sb + (k & 1) * SMSTAGE;
        uint32_t As_l = As_h + SM_AH;
        uint32_t Bs_h = As_l + SM_AL;
        uint32_t Bs_l = Bs_h + SM_BH;

#pragma unroll
        for (int t = 0; t < 4; t++) {
            uint32_t ah[2][4], al[2][4];
#pragma unroll
            for (int mi = 0; mi < 2; mi++) {
                int row = arow0 + mi * 16;
                uint32_t off = row * 128 + ((((2 * t) + ahalf) ^ (row & 7)) << 4);
                ldsm_x4(ah[mi][0], ah[mi][1], ah[mi][2], ah[mi][3], As_h + off);
                ldsm_x4(al[mi][0], al[mi][1], al[mi][2], al[mi][3], As_l + off);
            }
            uint32_t b[8][2];
#pragma unroll
            for (int j = 0; j < 4; j++) {          // Bh frags
                int n = bn0 + j * 16;
                uint32_t off = n * 128 + ((((2 * t) + bhalf) ^ (n & 7)) << 4);
                ldsm_x4(b[2 * j][0], b[2 * j][1], b[2 * j + 1][0], b[2 * j + 1][1], Bs_h + off);
            }
#pragma unroll
            for (int mi = 0; mi < 2; mi++)
#pragma unroll
                for (int nj = 0; nj < 8; nj++) {
                    mma16816(c[mi][nj], ah[mi], b[nj]);   // Ah @ Bh
                    mma16816(c[mi][nj], al[mi], b[nj]);   // Al @ Bh
                }
#pragma unroll
            for (int j = 0; j < 4; j++) {          // Bl frags (reuse b regs)
                int n = bn0 + j * 16;
                uint32_t off = n * 128 + ((((2 * t) + bhalf) ^ (n & 7)) << 4);
                ldsm_x4(b[2 * j][0], b[2 * j][1], b[2 * j + 1][0], b[2 * j + 1][1], Bs_l + off);
            }
#pragma unroll
            for (int mi = 0; mi < 2; mi++)
#pragma unroll
                for (int nj = 0; nj < 8; nj++)
                    mma16816(c[mi][nj], ah[mi], b[nj]);   // Ah @ Bl
        }
        __syncthreads();
        if (k + 2 < NCH) { loads(k + 2, k & 1); }
        cp_commit();
    }

#pragma unroll
    for (int mi = 0; mi < 2; mi++) {
        long row = bm + wm * 32 + mi * 16 + (lane >> 2);
        int g = (int)(row >> GSHIFT);
#pragma unroll
        for (int nj = 0; nj < 8; nj++) {
            int col = (int)bn + wn * 64 + nj * 8 + 2 * (lane & 3);
            float2 v0 = {c[mi][nj][0], c[mi][nj][1]};   // row
            float2 v1 = {c[mi][nj][2], c[mi][nj][3]};   // row + 8

            if (EPI == 3) {
                float b0 = bias[col], b1v = bias[col + 1];
                v0.x += b0; v0.y += b1v; v1.x += b0; v1.y += b1v;
                int rr = root_idx[g];
                if ((long)rr == row) {
                    h1root[g * 512 + col] = v0.x; h1root[g * 512 + col + 1] = v0.y;
                }
                if ((long)rr == row + 8) {
                    h1root[g * 512 + col] = v1.x; h1root[g * 512 + col + 1] = v1.y;
                }
                v0.x = fmaxf(v0.x, 0.f); v0.y = fmaxf(v0.y, 0.f);
                v1.x = fmaxf(v1.x, 0.f); v1.y = fmaxf(v1.y, 0.f);
                split_store2(Oh + row * 512 + col,       Ol + row * 512 + col,       v0);
                split_store2(Oh + (row + 8) * 512 + col, Ol + (row + 8) * 512 + col, v1);
            } else if (EPI == 4) {
                float s0 = S[row], s1 = S[row + 8];
                float r0 = rt[g * 512 + col], r1 = rt[g * 512 + col + 1];
                float b0 = bias[col], b1v = bias[col + 1];
                v0.x += b0 + s0 * r0; v0.y += b1v + s0 * r1;
                v1.x += b0 + s1 * r0; v1.y += b1v + s1 * r1;
                v0.x = fmaxf(v0.x, 0.f); v0.y = fmaxf(v0.y, 0.f);
                v1.x = fmaxf(v1.x, 0.f); v1.y = fmaxf(v1.y, 0.f);
                split_store2(Oh + row * 512 + col,       Ol + row * 512 + col,       v0);
                split_store2(Oh + (row + 8) * 512 + col, Ol + (row + 8) * 512 + col, v1);
            } else {  // EPI == 2
                float b0 = rt[g * 512 + col], b1v = rt[g * 512 + col + 1];
                v0.x += b0; v0.y += b1v; v1.x += b0; v1.y += b1v;
                v0.x = (v0.x >= 0.f) ? v0.x : 0.01f * v0.x;
                v0.y = (v0.y >= 0.f) ? v0.y : 0.01f * v0.y;
                v1.x = (v1.x >= 0.f) ? v1.x : 0.01f * v1.x;
                v1.y = (v1.y >= 0.f) ? v1.y : 0.01f * v1.y;
                *(float2*)(C + row * 512 + col)       = v0;
                *(float2*)(C + (row + 8) * 512 + col) = v1;
            }
        }
    }
}

// ---------------------------------------------------------------------------
// fused: split+transpose W1/W2a/Wla to bf16 hi/lo AND zero the CSR histogram
// ---------------------------------------------------------------------------
__global__ void split_w_zero_kernel(const float* __restrict__ W1,
                                    const float* __restrict__ W2,
                                    const float* __restrict__ Wl,
                                    __nv_bfloat16* __restrict__ w1h, __nv_bfloat16* __restrict__ w1l,
                                    __nv_bfloat16* __restrict__ w2h, __nv_bfloat16* __restrict__ w2l,
                                    __nv_bfloat16* __restrict__ wlh, __nv_bfloat16* __restrict__ wll,
                                    int* __restrict__ cnt)
{
    long idx = (long)blockIdx.x * blockDim.x + threadIdx.x;
    if (idx < MROWS) cnt[idx] = 0;
    if (idx >= 3 * 512 * 512) return;
    int which = (int)(idx >> 18);
    int loc   = (int)(idx & 0x3FFFF);
    int n = loc >> 9;
    int k = loc & 511;
    const float* W = (which == 0) ? W1 : (which == 1) ? W2 : Wl;
    __nv_bfloat16* wh = (which == 0) ? w1h : (which == 1) ? w2h : wlh;
    __nv_bfloat16* wl = (which == 0) ? w1l : (which == 1) ? w2l : wll;
    float x = __ldg(&W[(long)k * 512 + n]);
    __nv_bfloat16 h, l;
    split1(x, h, l);
    wh[loc] = h; wl[loc] = l;
}

// ---------------------------------------------------------------------------
// CSR build
// ---------------------------------------------------------------------------
__global__ void hist_kernel(const int* __restrict__ rows, int* __restrict__ cnt, int nE)
{
    int e = blockIdx.x * blockDim.x + threadIdx.x;
    if (e < nE) atomicAdd(&cnt[rows[e]], 1);
}
__global__ void __launch_bounds__(1024, 1)
scan_kernel(const int* __restrict__ cnt, int* __restrict__ offs, int* __restrict__ cursor)
{
    __shared__ int ts[1024];
    const int tid = threadIdx.x;
    const int base = tid * 64;
    int local = 0;
#pragma unroll 8
    for (int i = 0; i < 64; i++) local += cnt[base + i];
    int x = local;
    ts[tid] = x; __syncthreads();
    for (int s = 1; s < 1024; s <<= 1) {
        int v = (tid >= s) ? ts[tid - s] : 0;
        __syncthreads();
        x += v; ts[tid] = x; __syncthreads();
    }
    int run = x - local;
    for (int i = 0; i < 64; i++) {
        int cc = cnt[base + i];
        offs[base + i] = run;
        cursor[base + i] = run;
        run += cc;
    }
    if (tid == 1023) offs[MROWS] = run;
}
__global__ void fill_csr_kernel(const int* __restrict__ rows, const int* __restrict__ cols,
                                const float* __restrict__ vals, int* __restrict__ cursor,
                                int* __restrict__ ecol, float* __restrict__ ew, int nE)
{
    int e = blockIdx.x * blockDim.x + threadIdx.x;
    if (e >= nE) return;
    int p = atomicAdd(&cursor[rows[e]], 1);
    ecol[p] = cols[e];
    ew[p]   = vals[e];
}

// ---------------------------------------------------------------------------
// CSR gathers (one 128-thread block per destination row), 4-edge batching
// ---------------------------------------------------------------------------
__global__ void __launch_bounds__(128)
gather_f32_kernel(const float* __restrict__ src, const int* __restrict__ offs,
                  const int* __restrict__ ecol, const float* __restrict__ ew,
                  __nv_bfloat16* __restrict__ oh, __nv_bfloat16* __restrict__ ol,
                  float* __restrict__ S)
{
    const int r = blockIdx.x;
    const int tid = threadIdx.x;
    const int beg = __ldg(&offs[r]), end = __ldg(&offs[r + 1]);
    float4 acc = make_float4(0.f, 0.f, 0.f, 0.f);
    float s = 0.f;
    int i = beg;
    for (; i + 4 <= end; i += 4) {
        int c0 = __ldg(&ecol[i]),   c1 = __ldg(&ecol[i+1]);
        int c2 = __ldg(&ecol[i+2]), c3 = __ldg(&ecol[i+3]);
        float w0 = __ldg(&ew[i]),   w1 = __ldg(&ew[i+1]);
        float w2 = __ldg(&ew[i+2]), w3 = __ldg(&ew[i+3]);
        float4 v0 = __ldg((const float4*)(src + (long)c0 * 512) + tid);
        float4 v1 = __ldg((const float4*)(src + (long)c1 * 512) + tid);
        float4 v2 = __ldg((const float4*)(src + (long)c2 * 512) + tid);
        float4 v3 = __ldg((const float4*)(src + (long)c3 * 512) + tid);
        acc.x += w0*v0.x + w1*v1.x + w2*v2.x + w3*v3.x;
        acc.y += w0*v0.y + w1*v1.y + w2*v2.y + w3*v3.y;
        acc.z += w0*v0.z + w1*v1.z + w2*v2.z + w3*v3.z;
        acc.w += w0*v0.w + w1*v1.w + w2*v2.w + w3*v3.w;
        s += w0 + w1 + w2 + w3;
    }
    for (; i < end; i++) {
        int cc = __ldg(&ecol[i]);
        float w = __ldg(&ew[i]);
        float4 v = __ldg((const float4*)(src + (long)cc * 512) + tid);
        acc.x += w * v.x; acc.y += w * v.y; acc.z += w * v.z; acc.w += w * v.w;
        s += w;
    }
    if (tid == 0) S[r] = s;
    split_store4(oh + (long)r * 512 + tid * 4, ol + (long)r * 512 + tid * 4, acc);
}

__device__ __forceinline__ float4 ld_bf16pair(const __nv_bfloat16* sh,
                                              const __nv_bfloat16* sl,
                                              long row, int tid)
{
    const __nv_bfloat162* ph = (const __nv_bfloat162*)(sh + row * 512) + tid * 2;
    const __nv_bfloat162* pl = (const __nv_bfloat162*)(sl + row * 512) + tid * 2;
    __nv_bfloat162 h0 = __ldg(ph), h1 = __ldg(ph + 1);
    __nv_bfloat162 l0 = __ldg(pl), l1 = __ldg(pl + 1);
    float4 v;
    v.x = __bfloat162float(h0.x) + __bfloat162float(l0.x);
    v.y = __bfloat162float(h0.y) + __bfloat162float(l0.y);
    v.z = __bfloat162float(h1.x) + __bfloat162float(l1.x);
    v.w = __bfloat162float(h1.y) + __bfloat162float(l1.y);
    return v;
}

__global__ void __launch_bounds__(128)
gather_bf16_kernel(const __nv_bfloat16* __restrict__ sh, const __nv_bfloat16* __restrict__ sl,
                   const int* __restrict__ offs, const int* __restrict__ ecol,
                   const float* __restrict__ ew,
                   __nv_bfloat16* __restrict__ oh, __nv_bfloat16* __restrict__ ol)
{
    const int r = blockIdx.x;
    const int tid = threadIdx.x;
    const int beg = __ldg(&offs[r]), end = __ldg(&offs[r + 1]);
    float4 acc = make_float4(0.f, 0.f, 0.f, 0.f);
    int i = beg;
    for (; i + 4 <= end; i += 4) {
        int c0 = __ldg(&ecol[i]),   c1 = __ldg(&ecol[i+1]);
        int c2 = __ldg(&ecol[i+2]), c3 = __ldg(&ecol[i+3]);
        float w0 = __ldg(&ew[i]),   w1 = __ldg(&ew[i+1]);
        float w2 = __ldg(&ew[i+2]), w3 = __ldg(&ew[i+3]);
        float4 v0 = ld_bf16pair(sh, sl, c0, tid);
        float4 v1 = ld_bf16pair(sh, sl, c1, tid);
        float4 v2 = ld_bf16pair(sh, sl, c2, tid);
        float4 v3 = ld_bf16pair(sh, sl, c3, tid);
        acc.x += w0*v0.x + w1*v1.x + w2*v2.x + w3*v3.x;
        acc.y += w0*v0.y + w1*v1.y + w2*v2.y + w3*v3.y;
        acc.z += w0*v0.z + w1*v1.z + w2*v2.z + w3*v3.z;
        acc.w += w0*v0.w + w1*v1.w + w2*v2.w + w3*v3.w;
    }
    for (; i < end; i++) {
        int cc = __ldg(&ecol[i]);
        float w = __ldg(&ew[i]);
        float4 v = ld_bf16pair(sh, sl, cc, tid);
        acc.x += w * v.x; acc.y += w * v.y; acc.z += w * v.z; acc.w += w * v.w;
    }
    split_store4(oh + (long)r * 512 + tid * 4, ol + (long)r * 512 + tid * 4, acc);
}

// ---------------------------------------------------------------------------
// root terms
// ---------------------------------------------------------------------------
__global__ void init_rt_kernel(float* __restrict__ rt, float* __restrict__ rt2,
                               const float* __restrict__ bl)
{
    int idx = blockIdx.x * blockDim.x + threadIdx.x;
    if (idx >= NGRAPH * DFEAT) return;
    rt[idx] = 0.f;
    rt2[idx] = bl[idx & 511];
}
__global__ void __launch_bounds__(512)
root_term_kernel(const float* __restrict__ feat, const int* __restrict__ root_idx,
                 const float* __restrict__ W2, float* __restrict__ rt)
{
    int g  = blockIdx.x;
    int kc = blockIdx.y << 6;
    int n  = threadIdx.x;
    const float* v  = feat + (long)root_idx[g] * DFEAT + kc;
    const float* Wb = W2 + (long)(512 + kc) * 512 + n;
    float acc = 0.f;
#pragma unroll 8
    for (int k = 0; k < 64; k++)
        acc += fmaxf(__ldg(v + k), 0.f) * __ldg(Wb + (long)k * 512);
    atomicAdd(&rt[g * DFEAT + n], acc);
}
__global__ void __launch_bounds__(512)
root_term2_kernel(const float* __restrict__ h1root, const float* __restrict__ Wl,
                  float* __restrict__ rt2)
{
    int g  = blockIdx.x;
    int kc = blockIdx.y << 6;
    int n  = threadIdx.x;
    const float* v  = h1root + g * DFEAT + kc;
    const float* Wb = Wl + (long)(512 + kc) * 512 + n;
    float acc = 0.f;
#pragma unroll 8
    for (int k = 0; k < 64; k++)
        acc += __ldg(v + k) * __ldg(Wb + (long)k * 512);
    atomicAdd(&rt2[g * DFEAT + n], acc);
}

// ---------------------------------------------------------------------------
// launch
// ---------------------------------------------------------------------------
extern "C" void kernel_launch(void* const* d_in, const int* in_sizes, int n_in,
                              void* d_out, int out_size)
{
    const float* features = (const float*)d_in[0];
    const int*   adjs     = (const int*)  d_in[1];
    const float* values   = (const float*)d_in[2];
    const int*   root_idx = (const int*)  d_in[3];
    const float* W1 = (const float*)d_in[6];
    const float* b1 = (const float*)d_in[7];
    const float* W2 = (const float*)d_in[8];
    const float* b2 = (const float*)d_in[9];
    const float* Wl = (const float*)d_in[10];
    const float* bl = (const float*)d_in[11];
    float* out = (float*)d_out;

    const int nE = in_sizes[2];

    float *S, *rt, *rt2, *h1root, *ew;
    int *cnt, *offs, *cursor, *ecol;
    __nv_bfloat16 *ah, *al, *bh, *blo, *w1h, *w1l, *w2h, *w2l, *wlh, *wll;
    cudaGetSymbolAddress((void**)&S,      g_S);
    cudaGetSymbolAddress((void**)&rt,     g_rt);
    cudaGetSymbolAddress((void**)&rt2,    g_rt2);
    cudaGetSymbolAddress((void**)&h1root, g_h1root);
    cudaGetSymbolAddress((void**)&cnt,    g_cnt);
    cudaGetSymbolAddress((void**)&offs,   g_offs);
    cudaGetSymbolAddress((void**)&cursor, g_cursor);
    cudaGetSymbolAddress((void**)&ecol,   g_ecol);
    cudaGetSymbolAddress((void**)&ew,     g_ew);
    cudaGetSymbolAddress((void**)&ah,  g_ah);
    cudaGetSymbolAddress((void**)&al,  g_al);
    cudaGetSymbolAddress((void**)&bh,  g_bh);
    cudaGetSymbolAddress((void**)&blo, g_bl);
    cudaGetSymbolAddress((void**)&w1h, g_w1h);
    cudaGetSymbolAddress((void**)&w1l, g_w1l);
    cudaGetSymbolAddress((void**)&w2h, g_w2h);
    cudaGetSymbolAddress((void**)&w2l, g_w2l);
    cudaGetSymbolAddress((void**)&wlh, g_wlh);
    cudaGetSymbolAddress((void**)&wll, g_wll);

    const int* rows = adjs;
    const int* cols = adjs + nE;

    cudaFuncSetAttribute(gemm_bf16x3<3>, cudaFuncAttributeMaxDynamicSharedMemorySize, SMTOTAL);
    cudaFuncSetAttribute(gemm_bf16x3<4>, cudaFuncAttributeMaxDynamicSharedMemorySize, SMTOTAL);
    cudaFuncSetAttribute(gemm_bf16x3<2>, cudaFuncAttributeMaxDynamicSharedMemorySize, SMTOTAL);

    dim3 ggrid(DFEAT / BN2, MROWS / BM2);             // (2, 512)
    dim3 rtg(NGRAPH, 8);

    // #0: weight split + cnt zero
    split_w_zero_kernel<<<(3 * 512 * 512 + 255) / 256, 256>>>(
        W1, W2, Wl, w1h, w1l, w2h, w2l, wlh, wll, cnt);
    // #1-3: CSR build
    hist_kernel<<<(nE + 255) / 256, 256>>>(rows, cnt, nE);
    scan_kernel<<<1, 1024>>>(cnt, offs, cursor);
    fill_csr_kernel<<<(nE + 255) / 256, 256>>>(rows, cols, values, cursor, ecol, ew, nE);
    // #4: PX = P @ X (split bf16) + S
    gather_f32_kernel<<<MROWS, 128>>>(features, offs, ecol, ew, ah, al, S);
    // #5: h1 = PX @ W1 + b1 (root-store, relu, split) -> bh/blo
    gemm_bf16x3<3><<<ggrid, 512, SMTOTAL>>>(ah, al, w1h, w1l, nullptr,
                                            bh, blo, b1, nullptr, nullptr, root_idx, h1root);
    // #6-8: root terms
    init_rt_kernel<<<(NGRAPH * DFEAT + 255) / 256, 256>>>(rt, rt2, bl);
    root_term_kernel<<<rtg, 512>>>(features, root_idx, W2, rt);
    root_term2_kernel<<<rtg, 512>>>(h1root, Wl, rt2);
    // #9: Y = P @ relu(h1) (split bf16) -> ah/al
    gather_bf16_kernel<<<MROWS, 128>>>(bh, blo, offs, ecol, ew, ah, al);
    // #10: h2 = Y @ W2a + b2 + S*rt[g] (relu, split) -> bh/blo
    gemm_bf16x3<4><<<ggrid, 512, SMTOTAL>>>(ah, al, w2h, w2l, nullptr,
                                            bh, blo, b2, rt, S, nullptr, nullptr);
    // #11: out = leaky_relu(relu(h2) @ Wla + rt2[g])
    gemm_bf16x3<2><<<ggrid, 512, SMTOTAL>>>(bh, blo, wlh, wll, out,
                                            nullptr, nullptr, nullptr, rt2, nullptr, nullptr, nullptr);
}

// round 11
// speedup vs baseline: 1.3725x; 1.0276x over previous
#include <cuda_runtime.h>
#include <cuda_bf16.h>
#include <cstdint>

#define MROWS   65536
#define DFEAT   512
#define NEDGES  65536
#define NGRAPH  16
#define GSHIFT  12          // rows per graph = 4096

// ---------------------------------------------------------------------------
// Scratch (__device__ globals; allocation-free)
// ---------------------------------------------------------------------------
__device__ float g_S[MROWS];
__device__ float g_rt[NGRAPH * DFEAT];
__device__ float g_rt2[NGRAPH * DFEAT];
__device__ float g_h1root[NGRAPH * DFEAT];
__device__ __nv_bfloat16 g_ah[(size_t)MROWS * DFEAT], g_al[(size_t)MROWS * DFEAT];
__device__ __nv_bfloat16 g_bh[(size_t)MROWS * DFEAT], g_bl[(size_t)MROWS * DFEAT];
__device__ __nv_bfloat16 g_w1h[512 * 512], g_w1l[512 * 512];
__device__ __nv_bfloat16 g_w2h[512 * 512], g_w2l[512 * 512];
__device__ __nv_bfloat16 g_wlh[512 * 512], g_wll[512 * 512];
// CSR
__device__ int   g_cnt[MROWS];
__device__ int   g_offs[MROWS + 1];
__device__ int   g_cursor[MROWS];
__device__ int   g_ecol[NEDGES];
__device__ float g_ew[NEDGES];

// ---------------------------------------------------------------------------
// PTX helpers
// ---------------------------------------------------------------------------
__device__ __forceinline__ uint32_t smem_u32(const void* p) {
    return (uint32_t)__cvta_generic_to_shared(p);
}
__device__ __forceinline__ void cp_async16(uint32_t dst, const void* src) {
    asm volatile("cp.async.cg.shared.global [%0], [%1], 16;" :: "r"(dst), "l"(src));
}
__device__ __forceinline__ void cp_commit() {
    asm volatile("cp.async.commit_group;");
}
template<int N>
__device__ __forceinline__ void cp_wait() {
    asm volatile("cp.async.wait_group %0;" :: "n"(N));
}
__device__ __forceinline__ void ldsm_x4(uint32_t& r0, uint32_t& r1,
                                        uint32_t& r2, uint32_t& r3, uint32_t a) {
    asm volatile("ldmatrix.sync.aligned.m8n8.x4.shared.b16 {%0,%1,%2,%3}, [%4];"
                 : "=r"(r0), "=r"(r1), "=r"(r2), "=r"(r3) : "r"(a));
}
__device__ __forceinline__ void mma16816(float* c, const uint32_t* a, const uint32_t* b) {
    asm volatile(
        "mma.sync.aligned.m16n8k16.row.col.f32.bf16.bf16.f32 "
        "{%0,%1,%2,%3}, {%4,%5,%6,%7}, {%8,%9}, {%0,%1,%2,%3};"
        : "+f"(c[0]), "+f"(c[1]), "+f"(c[2]), "+f"(c[3])
        : "r"(a[0]), "r"(a[1]), "r"(a[2]), "r"(a[3]), "r"(b[0]), "r"(b[1]));
}

// ---------------------------------------------------------------------------
// split helpers
// ---------------------------------------------------------------------------
__device__ __forceinline__ void split1(float x, __nv_bfloat16& h, __nv_bfloat16& l) {
    h = __float2bfloat16_rn(x);
    l = __float2bfloat16_rn(x - __bfloat162float(h));
}
__device__ __forceinline__ void split_store2(__nv_bfloat16* ph, __nv_bfloat16* pl, float2 v) {
    __nv_bfloat16 h0, l0, h1, l1;
    split1(v.x, h0, l0); split1(v.y, h1, l1);
    __nv_bfloat162 hh, ll;
    hh.x = h0; hh.y = h1; ll.x = l0; ll.y = l1;
    *(__nv_bfloat162*)ph = hh; *(__nv_bfloat162*)pl = ll;
}
__device__ __forceinline__ void split_store4(__nv_bfloat16* ph, __nv_bfloat16* pl, float4 v) {
    split_store2(ph,     pl,     make_float2(v.x, v.y));
    split_store2(ph + 2, pl + 2, make_float2(v.z, v.w));
}

// ---------------------------------------------------------------------------
// bf16x3 FUSED-SEGMENT split GEMM, smem-read-optimized:
//   C = Ah@Bh^T + Al@Bh^T + Ah@Bl^T
// Warp tile 64x32 -> MAC:ldsm-byte ratio 16 (2x the 50%-capped R9/R10 loops).
// CTA 128x128, 256 thr (8 warps: 2M x 4N), 2 CTAs/SM.
// k32 chunks; each 128B smem row holds TWO k32 halves (16B-unit cols 0-3/4-7,
// disjoint under XOR swizzle) => built-in 2-stage pipeline in one 64KB buffer.
// EPI=3: +bias(col); fp32 root-row store; relu; split->Oh/Ol
// EPI=4: +bias(col)+S[row]*rt[g,col]; relu; split->Oh/Ol
// EPI=2: +rt2[g,col]; leaky_relu; fp32 store -> C
// ---------------------------------------------------------------------------
#define BM2 128
#define BN2 128
#define SM_M (BM2 * 128)                  // 16 KB per matrix buffer
#define SMTOTAL (4 * SM_M + 1024)         // Ah, Al, Bh, Bl  (~65 KB)

template<int EPI>
__global__ void __launch_bounds__(256, 2)
gemm_bf16x3(const __nv_bfloat16* __restrict__ Ah, const __nv_bfloat16* __restrict__ Al,
            const __nv_bfloat16* __restrict__ Bh, const __nv_bfloat16* __restrict__ Bl,
            float* __restrict__ C,
            __nv_bfloat16* __restrict__ Oh, __nv_bfloat16* __restrict__ Ol,
            const float* __restrict__ bias, const float* __restrict__ rt,
            const float* __restrict__ S, const int* __restrict__ root_idx,
            float* __restrict__ h1root)
{
    constexpr int K = 512;
    constexpr int NCH = 16;               // k32 chunks
    extern __shared__ char dsm[];
    uint32_t sb = (smem_u32(dsm) + 1023) & ~1023u;

    const int tid  = threadIdx.x;
    const int lane = tid & 31;
    const int wid  = tid >> 5;            // 0..7
    const int wm   = wid & 1;             // 2 M-warps (64 rows each)
    const int wn   = wid >> 1;            // 4 N-warps (32 cols each)
    const long bm  = (long)blockIdx.y * BM2;
    const long bn  = (long)blockIdx.x * BN2;

    const uint32_t As_h = sb;
    const uint32_t As_l = sb + SM_M;
    const uint32_t Bs_h = sb + 2 * SM_M;
    const uint32_t Bs_l = sb + 3 * SM_M;

    float c[4][4][4];
#pragma unroll
    for (int i = 0; i < 4; i++)
#pragma unroll
        for (int j = 0; j < 4; j++)
#pragma unroll
            for (int q = 0; q < 4; q++) c[i][j][q] = 0.0f;

    const int amat  = lane >> 3;
    const int arow0 = wm * 64 + (amat & 1) * 8 + (lane & 7);
    const int ahalf = amat >> 1;
    const int bg    = lane >> 3;
    const int bhalf = bg & 1;
    const int bn0   = wn * 32 + ((bg >> 1) << 3) + (lane & 7);

    const __nv_bfloat16* Ahp = Ah + bm * K;
    const __nv_bfloat16* Alp = Al + bm * K;
    const __nv_bfloat16* Bhp = Bh + bn * K;
    const __nv_bfloat16* Blp = Bl + bn * K;

    auto loads = [&](int ch) {
        int kk = ch << 5;                 // k offset (32 per chunk)
        int cb = (ch & 1) * 4;            // 16B-unit column base (half select)
#pragma unroll
        for (int i = 0; i < 2; i++) {
            int lin = tid * 2 + i;        // 0..511
            int r = lin >> 2;             // 0..127
            int u = lin & 3;              // 0..3
            uint32_t off = r * 128 + (((cb + u) ^ (r & 7)) << 4);
            long g = (long)r * K + kk + u * 8;
            cp_async16(As_h + off, Ahp + g);
            cp_async16(As_l + off, Alp + g);
            cp_async16(Bs_h + off, Bhp + g);
            cp_async16(Bs_l + off, Blp + g);
        }
    };

    loads(0); cp_commit();
    loads(1); cp_commit();

    for (int ch = 0; ch < NCH; ch++) {
        cp_wait<1>();
        __syncthreads();
        int cb = (ch & 1) * 4;
#pragma unroll
        for (int t = 0; t < 2; t++) {
            uint32_t ah[4][4], al[4][4];
#pragma unroll
            for (int mi = 0; mi < 4; mi++) {
                int row = arow0 + mi * 16;
                uint32_t off = row * 128 + (((cb + 2 * t + ahalf) ^ (row & 7)) << 4);
                ldsm_x4(ah[mi][0], ah[mi][1], ah[mi][2], ah[mi][3], As_h + off);
                ldsm_x4(al[mi][0], al[mi][1], al[mi][2], al[mi][3], As_l + off);
            }
            uint32_t b[4][2];
#pragma unroll
            for (int j = 0; j < 2; j++) {          // Bh frags
                int n = bn0 + j * 16;
                uint32_t off = n * 128 + (((cb + 2 * t + bhalf) ^ (n & 7)) << 4);
                ldsm_x4(b[2 * j][0], b[2 * j][1], b[2 * j + 1][0], b[2 * j + 1][1], Bs_h + off);
            }
#pragma unroll
            for (int mi = 0; mi < 4; mi++)
#pragma unroll
                for (int nj = 0; nj < 4; nj++) {
                    mma16816(c[mi][nj], ah[mi], b[nj]);   // Ah @ Bh
                    mma16816(c[mi][nj], al[mi], b[nj]);   // Al @ Bh
                }
#pragma unroll
            for (int j = 0; j < 2; j++) {          // Bl frags (reuse b regs)
                int n = bn0 + j * 16;
                uint32_t off = n * 128 + (((cb + 2 * t + bhalf) ^ (n & 7)) << 4);
                ldsm_x4(b[2 * j][0], b[2 * j][1], b[2 * j + 1][0], b[2 * j + 1][1], Bs_l + off);
            }
#pragma unroll
            for (int mi = 0; mi < 4; mi++)
#pragma unroll
                for (int nj = 0; nj < 4; nj++)
                    mma16816(c[mi][nj], ah[mi], b[nj]);   // Ah @ Bl
        }
        __syncthreads();                  // all warps done reading this half
        if (ch + 2 < NCH) loads(ch + 2);
        cp_commit();
    }

#pragma unroll
    for (int mi = 0; mi < 4; mi++) {
        long row = bm + wm * 64 + mi * 16 + (lane >> 2);
        int g = (int)(row >> GSHIFT);
#pragma unroll
        for (int nj = 0; nj < 4; nj++) {
            int col = (int)bn + wn * 32 + nj * 8 + 2 * (lane & 3);
            float2 v0 = {c[mi][nj][0], c[mi][nj][1]};   // row
            float2 v1 = {c[mi][nj][2], c[mi][nj][3]};   // row + 8

            if (EPI == 3) {
                float b0 = bias[col], b1v = bias[col + 1];
                v0.x += b0; v0.y += b1v; v1.x += b0; v1.y += b1v;
                int rr = root_idx[g];
                if ((long)rr == row) {
                    h1root[g * 512 + col] = v0.x; h1root[g * 512 + col + 1] = v0.y;
                }
                if ((long)rr == row + 8) {
                    h1root[g * 512 + col] = v1.x; h1root[g * 512 + col + 1] = v1.y;
                }
                v0.x = fmaxf(v0.x, 0.f); v0.y = fmaxf(v0.y, 0.f);
                v1.x = fmaxf(v1.x, 0.f); v1.y = fmaxf(v1.y, 0.f);
                split_store2(Oh + row * 512 + col,       Ol + row * 512 + col,       v0);
                split_store2(Oh + (row + 8) * 512 + col, Ol + (row + 8) * 512 + col, v1);
            } else if (EPI == 4) {
                float s0 = S[row], s1 = S[row + 8];
                float r0 = rt[g * 512 + col], r1 = rt[g * 512 + col + 1];
                float b0 = bias[col], b1v = bias[col + 1];
                v0.x += b0 + s0 * r0; v0.y += b1v + s0 * r1;
                v1.x += b0 + s1 * r0; v1.y += b1v + s1 * r1;
                v0.x = fmaxf(v0.x, 0.f); v0.y = fmaxf(v0.y, 0.f);
                v1.x = fmaxf(v1.x, 0.f); v1.y = fmaxf(v1.y, 0.f);
                split_store2(Oh + row * 512 + col,       Ol + row * 512 + col,       v0);
                split_store2(Oh + (row + 8) * 512 + col, Ol + (row + 8) * 512 + col, v1);
            } else {  // EPI == 2
                float b0 = rt[g * 512 + col], b1v = rt[g * 512 + col + 1];
                v0.x += b0; v0.y += b1v; v1.x += b0; v1.y += b1v;
                v0.x = (v0.x >= 0.f) ? v0.x : 0.01f * v0.x;
                v0.y = (v0.y >= 0.f) ? v0.y : 0.01f * v0.y;
                v1.x = (v1.x >= 0.f) ? v1.x : 0.01f * v1.x;
                v1.y = (v1.y >= 0.f) ? v1.y : 0.01f * v1.y;
                *(float2*)(C + row * 512 + col)       = v0;
                *(float2*)(C + (row + 8) * 512 + col) = v1;
            }
        }
    }
}

// ---------------------------------------------------------------------------
// fused: split+transpose W1/W2a/Wla to bf16 hi/lo AND zero the CSR histogram
// ---------------------------------------------------------------------------
__global__ void split_w_zero_kernel(const float* __restrict__ W1,
                                    const float* __restrict__ W2,
                                    const float* __restrict__ Wl,
                                    __nv_bfloat16* __restrict__ w1h, __nv_bfloat16* __restrict__ w1l,
                                    __nv_bfloat16* __restrict__ w2h, __nv_bfloat16* __restrict__ w2l,
                                    __nv_bfloat16* __restrict__ wlh, __nv_bfloat16* __restrict__ wll,
                                    int* __restrict__ cnt)
{
    long idx = (long)blockIdx.x * blockDim.x + threadIdx.x;
    if (idx < MROWS) cnt[idx] = 0;
    if (idx >= 3 * 512 * 512) return;
    int which = (int)(idx >> 18);
    int loc   = (int)(idx & 0x3FFFF);
    int n = loc >> 9;
    int k = loc & 511;
    const float* W = (which == 0) ? W1 : (which == 1) ? W2 : Wl;
    __nv_bfloat16* wh = (which == 0) ? w1h : (which == 1) ? w2h : wlh;
    __nv_bfloat16* wl = (which == 0) ? w1l : (which == 1) ? w2l : wll;
    float x = __ldg(&W[(long)k * 512 + n]);
    __nv_bfloat16 h, l;
    split1(x, h, l);
    wh[loc] = h; wl[loc] = l;
}

// ---------------------------------------------------------------------------
// CSR build
// ---------------------------------------------------------------------------
__global__ void hist_kernel(const int* __restrict__ rows, int* __restrict__ cnt, int nE)
{
    int e = blockIdx.x * blockDim.x + threadIdx.x;
    if (e < nE) atomicAdd(&cnt[rows[e]], 1);
}
__global__ void __launch_bounds__(1024, 1)
scan_kernel(const int* __restrict__ cnt, int* __restrict__ offs, int* __restrict__ cursor)
{
    __shared__ int ts[1024];
    const int tid = threadIdx.x;
    const int base = tid * 64;
    int local = 0;
#pragma unroll 8
    for (int i = 0; i < 64; i++) local += cnt[base + i];
    int x = local;
    ts[tid] = x; __syncthreads();
    for (int s = 1; s < 1024; s <<= 1) {
        int v = (tid >= s) ? ts[tid - s] : 0;
        __syncthreads();
        x += v; ts[tid] = x; __syncthreads();
    }
    int run = x - local;
    for (int i = 0; i < 64; i++) {
        int cc = cnt[base + i];
        offs[base + i] = run;
        cursor[base + i] = run;
        run += cc;
    }
    if (tid == 1023) offs[MROWS] = run;
}
__global__ void fill_csr_kernel(const int* __restrict__ rows, const int* __restrict__ cols,
                                const float* __restrict__ vals, int* __restrict__ cursor,
                                int* __restrict__ ecol, float* __restrict__ ew, int nE)
{
    int e = blockIdx.x * blockDim.x + threadIdx.x;
    if (e >= nE) return;
    int p = atomicAdd(&cursor[rows[e]], 1);
    ecol[p] = cols[e];
    ew[p]   = vals[e];
}

// ---------------------------------------------------------------------------
// CSR gathers (one 128-thread block per destination row), 4-edge batching
// ---------------------------------------------------------------------------
__global__ void __launch_bounds__(128)
gather_f32_kernel(const float* __restrict__ src, const int* __restrict__ offs,
                  const int* __restrict__ ecol, const float* __restrict__ ew,
                  __nv_bfloat16* __restrict__ oh, __nv_bfloat16* __restrict__ ol,
                  float* __restrict__ S)
{
    const int r = blockIdx.x;
    const int tid = threadIdx.x;
    const int beg = __ldg(&offs[r]), end = __ldg(&offs[r + 1]);
    float4 acc = make_float4(0.f, 0.f, 0.f, 0.f);
    float s = 0.f;
    int i = beg;
    for (; i + 4 <= end; i += 4) {
        int c0 = __ldg(&ecol[i]),   c1 = __ldg(&ecol[i+1]);
        int c2 = __ldg(&ecol[i+2]), c3 = __ldg(&ecol[i+3]);
        float w0 = __ldg(&ew[i]),   w1 = __ldg(&ew[i+1]);
        float w2 = __ldg(&ew[i+2]), w3 = __ldg(&ew[i+3]);
        float4 v0 = __ldg((const float4*)(src + (long)c0 * 512) + tid);
        float4 v1 = __ldg((const float4*)(src + (long)c1 * 512) + tid);
        float4 v2 = __ldg((const float4*)(src + (long)c2 * 512) + tid);
        float4 v3 = __ldg((const float4*)(src + (long)c3 * 512) + tid);
        acc.x += w0*v0.x + w1*v1.x + w2*v2.x + w3*v3.x;
        acc.y += w0*v0.y + w1*v1.y + w2*v2.y + w3*v3.y;
        acc.z += w0*v0.z + w1*v1.z + w2*v2.z + w3*v3.z;
        acc.w += w0*v0.w + w1*v1.w + w2*v2.w + w3*v3.w;
        s += w0 + w1 + w2 + w3;
    }
    for (; i < end; i++) {
        int cc = __ldg(&ecol[i]);
        float w = __ldg(&ew[i]);
        float4 v = __ldg((const float4*)(src + (long)cc * 512) + tid);
        acc.x += w * v.x; acc.y += w * v.y; acc.z += w * v.z; acc.w += w * v.w;
        s += w;
    }
    if (tid == 0) S[r] = s;
    split_store4(oh + (long)r * 512 + tid * 4, ol + (long)r * 512 + tid * 4, acc);
}

__device__ __forceinline__ float4 ld_bf16pair(const __nv_bfloat16* sh,
                                              const __nv_bfloat16* sl,
                                              long row, int tid)
{
    const __nv_bfloat162* ph = (const __nv_bfloat162*)(sh + row * 512) + tid * 2;
    const __nv_bfloat162* pl = (const __nv_bfloat162*)(sl + row * 512) + tid * 2;
    __nv_bfloat162 h0 = __ldg(ph), h1 = __ldg(ph + 1);
    __nv_bfloat162 l0 = __ldg(pl), l1 = __ldg(pl + 1);
    float4 v;
    v.x = __bfloat162float(h0.x) + __bfloat162float(l0.x);
    v.y = __bfloat162float(h0.y) + __bfloat162float(l0.y);
    v.z = __bfloat162float(h1.x) + __bfloat162float(l1.x);
    v.w = __bfloat162float(h1.y) + __bfloat162float(l1.y);
    return v;
}

__global__ void __launch_bounds__(128)
gather_bf16_kernel(const __nv_bfloat16* __restrict__ sh, const __nv_bfloat16* __restrict__ sl,
                   const int* __restrict__ offs, const int* __restrict__ ecol,
                   const float* __restrict__ ew,
                   __nv_bfloat16* __restrict__ oh, __nv_bfloat16* __restrict__ ol)
{
    const int r = blockIdx.x;
    const int tid = threadIdx.x;
    const int beg = __ldg(&offs[r]), end = __ldg(&offs[r + 1]);
    float4 acc = make_float4(0.f, 0.f, 0.f, 0.f);
    int i = beg;
    for (; i + 4 <= end; i += 4) {
        int c0 = __ldg(&ecol[i]),   c1 = __ldg(&ecol[i+1]);
        int c2 = __ldg(&ecol[i+2]), c3 = __ldg(&ecol[i+3]);
        float w0 = __ldg(&ew[i]),   w1 = __ldg(&ew[i+1]);
        float w2 = __ldg(&ew[i+2]), w3 = __ldg(&ew[i+3]);
        float4 v0 = ld_bf16pair(sh, sl, c0, tid);
        float4 v1 = ld_bf16pair(sh, sl, c1, tid);
        float4 v2 = ld_bf16pair(sh, sl, c2, tid);
        float4 v3 = ld_bf16pair(sh, sl, c3, tid);
        acc.x += w0*v0.x + w1*v1.x + w2*v2.x + w3*v3.x;
        acc.y += w0*v0.y + w1*v1.y + w2*v2.y + w3*v3.y;
        acc.z += w0*v0.z + w1*v1.z + w2*v2.z + w3*v3.z;
        acc.w += w0*v0.w + w1*v1.w + w2*v2.w + w3*v3.w;
    }
    for (; i < end; i++) {
        int cc = __ldg(&ecol[i]);
        float w = __ldg(&ew[i]);
        float4 v = ld_bf16pair(sh, sl, cc, tid);
        acc.x += w * v.x; acc.y += w * v.y; acc.z += w * v.z; acc.w += w * v.w;
    }
    split_store4(oh + (long)r * 512 + tid * 4, ol + (long)r * 512 + tid * 4, acc);
}

// ---------------------------------------------------------------------------
// root terms
// ---------------------------------------------------------------------------
__global__ void init_rt_kernel(float* __restrict__ rt, float* __restrict__ rt2,
                               const float* __restrict__ bl)
{
    int idx = blockIdx.x * blockDim.x + threadIdx.x;
    if (idx >= NGRAPH * DFEAT) return;
    rt[idx] = 0.f;
    rt2[idx] = bl[idx & 511];
}
__global__ void __launch_bounds__(512)
root_term_kernel(const float* __restrict__ feat, const int* __restrict__ root_idx,
                 const float* __restrict__ W2, float* __restrict__ rt)
{
    int g  = blockIdx.x;
    int kc = blockIdx.y << 6;
    int n  = threadIdx.x;
    const float* v  = feat + (long)root_idx[g] * DFEAT + kc;
    const float* Wb = W2 + (long)(512 + kc) * 512 + n;
    float acc = 0.f;
#pragma unroll 8
    for (int k = 0; k < 64; k++)
        acc += fmaxf(__ldg(v + k), 0.f) * __ldg(Wb + (long)k * 512);
    atomicAdd(&rt[g * DFEAT + n], acc);
}
__global__ void __launch_bounds__(512)
root_term2_kernel(const float* __restrict__ h1root, const float* __restrict__ Wl,
                  float* __restrict__ rt2)
{
    int g  = blockIdx.x;
    int kc = blockIdx.y << 6;
    int n  = threadIdx.x;
    const float* v  = h1root + g * DFEAT + kc;
    const float* Wb = Wl + (long)(512 + kc) * 512 + n;
    float acc = 0.f;
#pragma unroll 8
    for (int k = 0; k < 64; k++)
        acc += __ldg(v + k) * __ldg(Wb + (long)k * 512);
    atomicAdd(&rt2[g * DFEAT + n], acc);
}

// ---------------------------------------------------------------------------
// launch
// ---------------------------------------------------------------------------
extern "C" void kernel_launch(void* const* d_in, const int* in_sizes, int n_in,
                              void* d_out, int out_size)
{
    const float* features = (const float*)d_in[0];
    const int*   adjs     = (const int*)  d_in[1];
    const float* values   = (const float*)d_in[2];
    const int*   root_idx = (const int*)  d_in[3];
    const float* W1 = (const float*)d_in[6];
    const float* b1 = (const float*)d_in[7];
    const float* W2 = (const float*)d_in[8];
    const float* b2 = (const float*)d_in[9];
    const float* Wl = (const float*)d_in[10];
    const float* bl = (const float*)d_in[11];
    float* out = (float*)d_out;

    const int nE = in_sizes[2];

    float *S, *rt, *rt2, *h1root, *ew;
    int *cnt, *offs, *cursor, *ecol;
    __nv_bfloat16 *ah, *al, *bh, *blo, *w1h, *w1l, *w2h, *w2l, *wlh, *wll;
    cudaGetSymbolAddress((void**)&S,      g_S);
    cudaGetSymbolAddress((void**)&rt,     g_rt);
    cudaGetSymbolAddress((void**)&rt2,    g_rt2);
    cudaGetSymbolAddress((void**)&h1root, g_h1root);
    cudaGetSymbolAddress((void**)&cnt,    g_cnt);
    cudaGetSymbolAddress((void**)&offs,   g_offs);
    cudaGetSymbolAddress((void**)&cursor, g_cursor);
    cudaGetSymbolAddress((void**)&ecol,   g_ecol);
    cudaGetSymbolAddress((void**)&ew,     g_ew);
    cudaGetSymbolAddress((void**)&ah,  g_ah);
    cudaGetSymbolAddress((void**)&al,  g_al);
    cudaGetSymbolAddress((void**)&bh,  g_bh);
    cudaGetSymbolAddress((void**)&blo, g_bl);
    cudaGetSymbolAddress((void**)&w1h, g_w1h);
    cudaGetSymbolAddress((void**)&w1l, g_w1l);
    cudaGetSymbolAddress((void**)&w2h, g_w2h);
    cudaGetSymbolAddress((void**)&w2l, g_w2l);
    cudaGetSymbolAddress((void**)&wlh, g_wlh);
    cudaGetSymbolAddress((void**)&wll, g_wll);

    const int* rows = adjs;
    const int* cols = adjs + nE;

    cudaFuncSetAttribute(gemm_bf16x3<3>, cudaFuncAttributeMaxDynamicSharedMemorySize, SMTOTAL);
    cudaFuncSetAttribute(gemm_bf16x3<4>, cudaFuncAttributeMaxDynamicSharedMemorySize, SMTOTAL);
    cudaFuncSetAttribute(gemm_bf16x3<2>, cudaFuncAttributeMaxDynamicSharedMemorySize, SMTOTAL);

    dim3 ggrid(DFEAT / BN2, MROWS / BM2);             // (4, 512)
    dim3 rtg(NGRAPH, 8);

    // #0: weight split + cnt zero
    split_w_zero_kernel<<<(3 * 512 * 512 + 255) / 256, 256>>>(
        W1, W2, Wl, w1h, w1l, w2h, w2l, wlh, wll, cnt);
    // #1-3: CSR build
    hist_kernel<<<(nE + 255) / 256, 256>>>(rows, cnt, nE);
    scan_kernel<<<1, 1024>>>(cnt, offs, cursor);
    fill_csr_kernel<<<(nE + 255) / 256, 256>>>(rows, cols, values, cursor, ecol, ew, nE);
    // #4: PX = P @ X (split bf16) + S
    gather_f32_kernel<<<MROWS, 128>>>(features, offs, ecol, ew, ah, al, S);
    // #5: h1 = PX @ W1 + b1 (root-store, relu, split) -> bh/blo
    gemm_bf16x3<3><<<ggrid, 256, SMTOTAL>>>(ah, al, w1h, w1l, nullptr,
                                            bh, blo, b1, nullptr, nullptr, root_idx, h1root);
    // #6-8: root terms
    init_rt_kernel<<<(NGRAPH * DFEAT + 255) / 256, 256>>>(rt, rt2, bl);
    root_term_kernel<<<rtg, 512>>>(features, root_idx, W2, rt);
    root_term2_kernel<<<rtg, 512>>>(h1root, Wl, rt2);
    // #9: Y = P @ relu(h1) (split bf16) -> ah/al
    gather_bf16_kernel<<<MROWS, 128>>>(bh, blo, offs, ecol, ew, ah, al);
    // #10: h2 = Y @ W2a + b2 + S*rt[g] (relu, split) -> bh/blo
    gemm_bf16x3<4><<<ggrid, 256, SMTOTAL>>>(ah, al, w2h, w2l, nullptr,
                                            bh, blo, b2, rt, S, nullptr, nullptr);
    // #11: out = leaky_relu(relu(h2) @ Wla + rt2[g])
    gemm_bf16x3<2><<<ggrid, 256, SMTOTAL>>>(bh, blo, wlh, wll, out,
                                            nullptr, nullptr, nullptr, rt2, nullptr, nullptr, nullptr);
}